// round 11
// baseline (speedup 1.0000x reference)
#include <cuda_runtime.h>
#include <cuda_bf16.h>
#include <math.h>
#include <stdint.h>

#define DIMC   1024
#define BATCH  2
#define SEQ    2048
#define MTOT   (BATCH*SEQ)      /* 4096 rows */
#define NHEAD  16
#define HD     64
#define QSCALE 0.125f           /* 64^-0.5 */

/* ------------------- scratch (allocations forbidden) ------------------- */
__device__ float g_Q  [MTOT * DIMC];
__device__ float g_K  [MTOT * DIMC];
__device__ float g_V  [MTOT * DIMC];
__device__ float g_OUT[MTOT * DIMC];
__device__ float g_H1 [MTOT * DIMC];
__device__ float g_Mpart[16 * BATCH * NHEAD * HD * HD];
__device__ float g_M  [BATCH * NHEAD * HD * HD];

/* bf16 split operands */
__device__ __nv_bfloat16 g_xh [MTOT * DIMC], g_xl [MTOT * DIMC];
__device__ __nv_bfloat16 g_oh [MTOT * DIMC], g_ol [MTOT * DIMC];
__device__ __nv_bfloat16 g_hh [MTOT * DIMC], g_hl [MTOT * DIMC];
__device__ __nv_bfloat16 g_wqh[DIMC * DIMC], g_wql[DIMC * DIMC];
__device__ __nv_bfloat16 g_wkh[DIMC * DIMC], g_wkl[DIMC * DIMC];
__device__ __nv_bfloat16 g_wvh[DIMC * DIMC], g_wvl[DIMC * DIMC];
__device__ __nv_bfloat16 g_w1h[DIMC * DIMC], g_w1l[DIMC * DIMC];
__device__ __nv_bfloat16 g_w2h[DIMC * DIMC], g_w2l[DIMC * DIMC];

/* ============================ asm helpers =============================== */
__device__ __forceinline__ uint32_t smem_u32(const void* p) {
    uint32_t a;
    asm("{ .reg .u64 t; cvta.to.shared.u64 t, %1; cvt.u32.u64 %0, t; }"
        : "=r"(a) : "l"(p));
    return a;
}
#define CP_ASYNC16(saddr, gptr) \
    asm volatile("cp.async.cg.shared.global [%0], [%1], 16;" \
                 :: "r"(saddr), "l"(gptr) : "memory")
#define CP_COMMIT()  asm volatile("cp.async.commit_group;" ::: "memory")
#define CP_WAIT(N)   asm volatile("cp.async.wait_group %0;" :: "n"(N) : "memory")

__device__ __forceinline__ void ldsm_x4(uint32_t& r0, uint32_t& r1,
                                        uint32_t& r2, uint32_t& r3, uint32_t addr) {
    asm volatile("ldmatrix.sync.aligned.m8n8.x4.shared.b16 {%0,%1,%2,%3}, [%4];"
                 : "=r"(r0), "=r"(r1), "=r"(r2), "=r"(r3) : "r"(addr));
}
__device__ __forceinline__ void mma_bf16(float* c, const uint32_t* a,
                                         uint32_t b0, uint32_t b1) {
    asm volatile(
        "mma.sync.aligned.m16n8k16.row.col.f32.bf16.bf16.f32 "
        "{%0,%1,%2,%3},{%4,%5,%6,%7},{%8,%9},{%0,%1,%2,%3};"
        : "+f"(c[0]), "+f"(c[1]), "+f"(c[2]), "+f"(c[3])
        : "r"(a[0]), "r"(a[1]), "r"(a[2]), "r"(a[3]), "r"(b0), "r"(b1));
}

/* =========================================================================
 * bf16x3 GEMM (mma.sync.m16n8k16):
 *   C[m,n] = epi( sum_k A[m,k]*B[n,k] + bias[n] )
 *   A ~ Ah+Al, B ~ Bh+Bl (bf16).  acc += AhBh + AhBl + AlBh  (fp32)
 * Tile 128x128, BK=32, cp.async double buffer, 256 threads, 2 CTAs/SM.
 * smem rows padded to 80B (bank-conflict-free ldmatrix/lds).
 * EPI: 0 = (acc+bias)*alpha ; 1 = gelu_exact ; 2 = acc+bias+r1+r2
 * ========================================================================= */
#define TM 128
#define TN 128
#define BK 32
#define NCH (DIMC / BK)            /* 32 k-chunks */
#define PADB 80                    /* bytes per smem row (32 bf16 + pad) */
#define TILE_B (128 * PADB)        /* 10240 */
#define STAGE_B (4 * TILE_B)       /* Ah, Al, Bh, Bl */
#define GSMEM_DYN (2 * STAGE_B)    /* 81920 */

template<int EPI>
__global__ void __launch_bounds__(256, 2)
gemm_bf16x3(const __nv_bfloat16* __restrict__ Ah, const __nv_bfloat16* __restrict__ Al,
            const __nv_bfloat16* __restrict__ Bh, const __nv_bfloat16* __restrict__ Bl,
            const float* __restrict__ bias, float* __restrict__ C,
            float alpha, const float* __restrict__ r1, const float* __restrict__ r2)
{
    extern __shared__ char smem[];
    const uint32_t sbase = smem_u32(smem);

    const int tid  = threadIdx.x;
    const int wid  = tid >> 5;
    const int lane = tid & 31;
    const int wm   = wid >> 2;     /* 0..1  -> 64-row slice  */
    const int wn   = wid & 3;      /* 0..3  -> 32-col slice  */
    const int g    = lane >> 2;    /* group 0..7 */
    const int t    = lane & 3;
    const int m0   = blockIdx.y * TM;
    const int n0   = blockIdx.x * TN;

    const char* srcs[4];
    srcs[0] = (const char*)(Ah + (size_t)m0 * DIMC);
    srcs[1] = (const char*)(Al + (size_t)m0 * DIMC);
    srcs[2] = (const char*)(Bh + (size_t)n0 * DIMC);
    srcs[3] = (const char*)(Bl + (size_t)n0 * DIMC);

    /* per-thread cp.async mapping: 8 x 16B chunks per stage */
    int cid[8], crow[8], ccol[8];
#pragma unroll
    for (int it = 0; it < 8; it++) {
        int id = tid + it * 256;           /* 0..2047 */
        cid[it]  = id >> 9;                /* tile 0..3     */
        crow[it] = (id >> 2) & 127;        /* row 0..127    */
        ccol[it] = id & 3;                 /* 16B chunk 0..3 */
    }

    auto prefetch = [&](int ch, int buf) {
        const uint32_t sb = sbase + buf * STAGE_B;
#pragma unroll
        for (int it = 0; it < 8; it++) {
            const char* gp = srcs[cid[it]] + (size_t)crow[it] * (DIMC * 2)
                           + ch * (BK * 2) + ccol[it] * 16;
            uint32_t sa = sb + cid[it] * TILE_B + crow[it] * PADB + ccol[it] * 16;
            CP_ASYNC16(sa, gp);
        }
        CP_COMMIT();
    };

    float acc[4][4][4];
#pragma unroll
    for (int i = 0; i < 4; i++)
#pragma unroll
        for (int j = 0; j < 4; j++)
#pragma unroll
            for (int q = 0; q < 4; q++) acc[i][j][q] = 0.0f;

    prefetch(0, 0);

    /* ldmatrix lane address offset: row (lane&15), col-half (lane>>4) */
    const uint32_t lm_off = (uint32_t)(lane & 15) * PADB + (uint32_t)(lane >> 4) * 16;

    for (int ch = 0; ch < NCH; ch++) {
        const int buf = ch & 1;
        if (ch + 1 < NCH) { prefetch(ch + 1, buf ^ 1); CP_WAIT(1); }
        else              { CP_WAIT(0); }
        __syncthreads();

        const uint32_t sb   = sbase + buf * STAGE_B;
        const uint32_t aht  = sb;
        const uint32_t alt  = sb + TILE_B;
        const uint32_t bht  = sb + 2 * TILE_B;
        const uint32_t blt  = sb + 3 * TILE_B;

#pragma unroll
        for (int ks = 0; ks < 2; ks++) {          /* two k16 steps per BK=32 */
            /* B fragments: b0 @ k=2t, b1 @ k=2t+8 (bytes +16) */
            uint32_t bh[4][2], bl[4][2];
#pragma unroll
            for (int j = 0; j < 4; j++) {
                uint32_t nrow = (uint32_t)(wn * 32 + j * 8 + g) * PADB + ks * 32 + t * 4;
                asm volatile("ld.shared.b32 %0, [%1];" : "=r"(bh[j][0]) : "r"(bht + nrow));
                asm volatile("ld.shared.b32 %0, [%1];" : "=r"(bh[j][1]) : "r"(bht + nrow + 16));
                asm volatile("ld.shared.b32 %0, [%1];" : "=r"(bl[j][0]) : "r"(blt + nrow));
                asm volatile("ld.shared.b32 %0, [%1];" : "=r"(bl[j][1]) : "r"(blt + nrow + 16));
            }
#pragma unroll
            for (int i = 0; i < 4; i++) {
                uint32_t arow = (uint32_t)(wm * 64 + i * 16) * PADB + lm_off + ks * 32;
                uint32_t ah[4], al[4];
                ldsm_x4(ah[0], ah[1], ah[2], ah[3], aht + arow);
                ldsm_x4(al[0], al[1], al[2], al[3], alt + arow);
#pragma unroll
                for (int j = 0; j < 4; j++) {
                    mma_bf16(acc[i][j], ah, bh[j][0], bh[j][1]);
                    mma_bf16(acc[i][j], ah, bl[j][0], bl[j][1]);
                    mma_bf16(acc[i][j], al, bh[j][0], bh[j][1]);
                }
            }
        }
        __syncthreads();
    }

    /* ---------------- epilogue: register-resident ---------------- */
#pragma unroll
    for (int i = 0; i < 4; i++) {
        const int row0 = m0 + wm * 64 + i * 16 + g;
#pragma unroll
        for (int j = 0; j < 4; j++) {
            const int col = n0 + wn * 32 + j * 8 + 2 * t;
            float2 b2 = *(const float2*)(bias + col);
            float v[4] = { acc[i][j][0] + b2.x, acc[i][j][1] + b2.y,
                           acc[i][j][2] + b2.x, acc[i][j][3] + b2.y };
            size_t p0 = (size_t)row0 * DIMC + col;
            size_t p1 = (size_t)(row0 + 8) * DIMC + col;
            if (EPI == 0) {
#pragma unroll
                for (int q = 0; q < 4; q++) v[q] *= alpha;
            } else if (EPI == 1) {
#pragma unroll
                for (int q = 0; q < 4; q++)
                    v[q] = 0.5f * v[q] * (1.0f + erff(v[q] * 0.70710678118654752f));
            } else {
                float2 x0 = *(const float2*)(r1 + p0), o0 = *(const float2*)(r2 + p0);
                float2 x1 = *(const float2*)(r1 + p1), o1 = *(const float2*)(r2 + p1);
                v[0] += x0.x + o0.x; v[1] += x0.y + o0.y;
                v[2] += x1.x + o1.x; v[3] += x1.y + o1.y;
            }
            *(float2*)(C + p0) = make_float2(v[0], v[1]);
            *(float2*)(C + p1) = make_float2(v[2], v[3]);
        }
    }
}

/* ================== fp32 -> bf16 (hi, lo) split ========================= */
__global__ void split_kernel(const float* __restrict__ in,
                             __nv_bfloat16* __restrict__ hi,
                             __nv_bfloat16* __restrict__ lo, int n)
{
    int i = (blockIdx.x * 256 + threadIdx.x) * 4;
    if (i >= n) return;
    float4 v = *(const float4*)(in + i);
    __nv_bfloat16 h[4], l[4];
    float f[4] = {v.x, v.y, v.z, v.w};
#pragma unroll
    for (int k = 0; k < 4; k++) {
        h[k] = __float2bfloat16(f[k]);
        l[k] = __float2bfloat16(f[k] - __bfloat162float(h[k]));
    }
    ushort4 hv, lv;
    hv.x = *(unsigned short*)&h[0]; hv.y = *(unsigned short*)&h[1];
    hv.z = *(unsigned short*)&h[2]; hv.w = *(unsigned short*)&h[3];
    lv.x = *(unsigned short*)&l[0]; lv.y = *(unsigned short*)&l[1];
    lv.z = *(unsigned short*)&l[2]; lv.w = *(unsigned short*)&l[3];
    *(ushort4*)(hi + i) = hv;
    *(ushort4*)(lo + i) = lv;
}

/* =========================================================================
 * Attention middle (exact fp32):  M_h = K_h^T V_h ;  OUT = Q_h @ M_h
 * ========================================================================= */
__global__ void __launch_bounds__(256)
kv_m_kernel(const float* __restrict__ K, const float* __restrict__ V,
            float* __restrict__ Mp)
{
    __shared__ float Ks[16][68];
    __shared__ float Vs[16][68];

    const int bh = blockIdx.x;               /* b*16 + h */
    const int b  = bh >> 4, h = bh & 15;
    const int s0 = blockIdx.y * 128;
    const int tid = threadIdx.x;
    const int e0 = (tid >> 4) * 4;
    const int d0 = (tid & 15) * 4;

    float acc[4][4] = {};
    const int lr = tid >> 4;
    const int lc = (tid & 15) * 4;

    for (int st = 0; st < 128; st += 16) {
        size_t gi = ((size_t)(b * SEQ + s0 + st + lr)) * DIMC + h * HD + lc;
        *(float4*)&Ks[lr][lc] = *(const float4*)(K + gi);
        *(float4*)&Vs[lr][lc] = *(const float4*)(V + gi);
        __syncthreads();
#pragma unroll
        for (int ss = 0; ss < 16; ss++) {
            float kv[4], vv[4];
#pragma unroll
            for (int i = 0; i < 4; i++) { kv[i] = Ks[ss][e0 + i]; vv[i] = Vs[ss][d0 + i]; }
#pragma unroll
            for (int i = 0; i < 4; i++)
#pragma unroll
                for (int jj = 0; jj < 4; jj++) acc[i][jj] += kv[i] * vv[jj];
        }
        __syncthreads();
    }

    float* mo = Mp + ((size_t)blockIdx.y * 32 + bh) * (HD * HD);
#pragma unroll
    for (int i = 0; i < 4; i++)
#pragma unroll
        for (int jj = 0; jj < 4; jj++)
            mo[(e0 + i) * HD + d0 + jj] = acc[i][jj];
}

__global__ void reduce_m_kernel(const float* __restrict__ Mp, float* __restrict__ Mo)
{
    int i = blockIdx.x * 256 + threadIdx.x;   /* 0 .. 32*4096-1 */
    float s = 0.0f;
#pragma unroll
    for (int p = 0; p < 16; p++) s += Mp[(size_t)p * 32 * HD * HD + i];
    Mo[i] = s;
}

__global__ void __launch_bounds__(256)
qm_kernel(const float* __restrict__ Q, const float* __restrict__ Mi,
          float* __restrict__ O)
{
    __shared__ float Qs[64][68];
    __shared__ float Ms[64][68];

    const int bh = blockIdx.x;
    const int b  = bh >> 4, h = bh & 15;
    const int s0 = blockIdx.y * 64;
    const int tid = threadIdx.x;

#pragma unroll
    for (int p = 0; p < 4; p++) {
        int slot = tid + p * 256;
        int r = slot >> 4;
        int c = (slot & 15) * 4;
        *(float4*)&Qs[r][c] = *(const float4*)(Q + ((size_t)(b * SEQ + s0 + r)) * DIMC + h * HD + c);
        *(float4*)&Ms[r][c] = *(const float4*)(Mi + (size_t)bh * HD * HD + r * HD + c);
    }
    __syncthreads();

    const int r0 = (tid >> 4) * 4;
    const int c0 = (tid & 15) * 4;
    float acc[4][4] = {};
#pragma unroll
    for (int k = 0; k < 64; k++) {
        float qv[4], mv[4];
#pragma unroll
        for (int i = 0; i < 4; i++) qv[i] = Qs[r0 + i][k];
#pragma unroll
        for (int jj = 0; jj < 4; jj++) mv[jj] = Ms[k][c0 + jj];
#pragma unroll
        for (int i = 0; i < 4; i++)
#pragma unroll
            for (int jj = 0; jj < 4; jj++) acc[i][jj] += qv[i] * mv[jj];
    }
#pragma unroll
    for (int i = 0; i < 4; i++)
#pragma unroll
        for (int jj = 0; jj < 4; jj++)
            O[((size_t)(b * SEQ + s0 + r0 + i)) * DIMC + h * HD + c0 + jj] = acc[i][jj];
}

/* ========================================================================= */
extern "C" void kernel_launch(void* const* d_in, const int* in_sizes, int n_in,
                              void* d_out, int out_size)
{
    const float* x  = (const float*)d_in[0];
    const float* Wq = (const float*)d_in[1];
    const float* bq = (const float*)d_in[2];
    const float* Wk = (const float*)d_in[3];
    const float* bk = (const float*)d_in[4];
    const float* Wv = (const float*)d_in[5];
    const float* bv = (const float*)d_in[6];
    const float* W1 = (const float*)d_in[7];
    const float* b1 = (const float*)d_in[8];
    const float* W2 = (const float*)d_in[9];
    const float* b2 = (const float*)d_in[10];
    float* Y = (float*)d_out;

    float *Q, *K, *V, *OUTP, *H1, *MP, *MM;
    cudaGetSymbolAddress((void**)&Q,    g_Q);
    cudaGetSymbolAddress((void**)&K,    g_K);
    cudaGetSymbolAddress((void**)&V,    g_V);
    cudaGetSymbolAddress((void**)&OUTP, g_OUT);
    cudaGetSymbolAddress((void**)&H1,   g_H1);
    cudaGetSymbolAddress((void**)&MP,   g_Mpart);
    cudaGetSymbolAddress((void**)&MM,   g_M);

    __nv_bfloat16 *xh, *xl, *oh, *ol, *hh, *hl;
    __nv_bfloat16 *wqh, *wql, *wkh, *wkl, *wvh, *wvl, *w1h, *w1l, *w2h, *w2l;
    cudaGetSymbolAddress((void**)&xh,  g_xh);  cudaGetSymbolAddress((void**)&xl,  g_xl);
    cudaGetSymbolAddress((void**)&oh,  g_oh);  cudaGetSymbolAddress((void**)&ol,  g_ol);
    cudaGetSymbolAddress((void**)&hh,  g_hh);  cudaGetSymbolAddress((void**)&hl,  g_hl);
    cudaGetSymbolAddress((void**)&wqh, g_wqh); cudaGetSymbolAddress((void**)&wql, g_wql);
    cudaGetSymbolAddress((void**)&wkh, g_wkh); cudaGetSymbolAddress((void**)&wkl, g_wkl);
    cudaGetSymbolAddress((void**)&wvh, g_wvh); cudaGetSymbolAddress((void**)&wvl, g_wvl);
    cudaGetSymbolAddress((void**)&w1h, g_w1h); cudaGetSymbolAddress((void**)&w1l, g_w1l);
    cudaGetSymbolAddress((void**)&w2h, g_w2h); cudaGetSymbolAddress((void**)&w2l, g_w2l);

    cudaFuncSetAttribute(gemm_bf16x3<0>, cudaFuncAttributeMaxDynamicSharedMemorySize, GSMEM_DYN);
    cudaFuncSetAttribute(gemm_bf16x3<1>, cudaFuncAttributeMaxDynamicSharedMemorySize, GSMEM_DYN);
    cudaFuncSetAttribute(gemm_bf16x3<2>, cudaFuncAttributeMaxDynamicSharedMemorySize, GSMEM_DYN);

    const int NX = MTOT * DIMC;   /* 4.19M */
    const int NW = DIMC * DIMC;   /* 1.05M */
    dim3 sgx((NX / 4 + 255) / 256), sgw((NW / 4 + 255) / 256);

    /* bf16 splits of activations & weights */
    split_kernel<<<sgx, 256>>>(x,  xh,  xl,  NX);
    split_kernel<<<sgw, 256>>>(Wq, wqh, wql, NW);
    split_kernel<<<sgw, 256>>>(Wk, wkh, wkl, NW);
    split_kernel<<<sgw, 256>>>(Wv, wvh, wvl, NW);
    split_kernel<<<sgw, 256>>>(W1, w1h, w1l, NW);
    split_kernel<<<sgw, 256>>>(W2, w2h, w2l, NW);

    dim3 ggrid(DIMC / TN, MTOT / TM);   /* (8, 32) */

    /* projections (bf16x3 on HMMA tensor cores) */
    gemm_bf16x3<0><<<ggrid, 256, GSMEM_DYN>>>(xh, xl, wqh, wql, bq, Q, QSCALE, nullptr, nullptr);
    gemm_bf16x3<0><<<ggrid, 256, GSMEM_DYN>>>(xh, xl, wkh, wkl, bk, K, 1.0f,   nullptr, nullptr);
    gemm_bf16x3<0><<<ggrid, 256, GSMEM_DYN>>>(xh, xl, wvh, wvl, bv, V, 1.0f,   nullptr, nullptr);

    /* attention collapsed: out = Q @ (K^T V) per head, exact fp32 */
    kv_m_kernel<<<dim3(32, 16), 256>>>(K, V, MP);
    reduce_m_kernel<<<(32 * HD * HD) / 256, 256>>>(MP, MM);
    qm_kernel<<<dim3(32, SEQ / 64), 256>>>(Q, MM, OUTP);

    /* MLP: h = gelu(OUT @ W1^T + b1); Y = x + OUT + (h @ W2^T + b2) */
    split_kernel<<<sgx, 256>>>(OUTP, oh, ol, NX);
    gemm_bf16x3<1><<<ggrid, 256, GSMEM_DYN>>>(oh, ol, w1h, w1l, b1, H1, 1.0f, nullptr, nullptr);
    split_kernel<<<sgx, 256>>>(H1, hh, hl, NX);
    gemm_bf16x3<2><<<ggrid, 256, GSMEM_DYN>>>(hh, hl, w2h, w2l, b2, Y, 1.0f, x, OUTP);
}

// round 12
// speedup vs baseline: 1.3464x; 1.3464x over previous
#include <cuda_runtime.h>
#include <cuda_fp16.h>
#include <math.h>
#include <stdint.h>

#define DIMC   1024
#define BATCH  2
#define SEQ    2048
#define MTOT   (BATCH*SEQ)      /* 4096 rows */
#define NHEAD  16
#define HD     64
#define QSCALE 0.125f           /* 64^-0.5 */

/* ------------------- scratch (allocations forbidden) ------------------- */
__device__ float g_Q  [MTOT * DIMC];
__device__ float g_K  [MTOT * DIMC];
__device__ float g_V  [MTOT * DIMC];
__device__ float g_OUT[MTOT * DIMC];
__device__ float g_Mpart[16 * BATCH * NHEAD * HD * HD];
__device__ float g_M  [BATCH * NHEAD * HD * HD];

/* fp16 split operands */
__device__ __half g_xh [MTOT * DIMC], g_xl [MTOT * DIMC];
__device__ __half g_oh [MTOT * DIMC], g_ol [MTOT * DIMC];
__device__ __half g_hh [MTOT * DIMC], g_hl [MTOT * DIMC];
__device__ __half g_wqh[DIMC * DIMC], g_wql[DIMC * DIMC];
__device__ __half g_wkh[DIMC * DIMC], g_wkl[DIMC * DIMC];
__device__ __half g_wvh[DIMC * DIMC], g_wvl[DIMC * DIMC];
__device__ __half g_w1h[DIMC * DIMC], g_w1l[DIMC * DIMC];
__device__ __half g_w2h[DIMC * DIMC], g_w2l[DIMC * DIMC];

/* ============================ asm helpers =============================== */
__device__ __forceinline__ uint32_t smem_u32(const void* p) {
    uint32_t a;
    asm("{ .reg .u64 t; cvta.to.shared.u64 t, %1; cvt.u32.u64 %0, t; }"
        : "=r"(a) : "l"(p));
    return a;
}
#define CP_ASYNC16(saddr, gptr) \
    asm volatile("cp.async.cg.shared.global [%0], [%1], 16;" \
                 :: "r"(saddr), "l"(gptr) : "memory")
#define CP_COMMIT()  asm volatile("cp.async.commit_group;" ::: "memory")
#define CP_WAIT(N)   asm volatile("cp.async.wait_group %0;" :: "n"(N) : "memory")

__device__ __forceinline__ void ldsm_x4(uint32_t& r0, uint32_t& r1,
                                        uint32_t& r2, uint32_t& r3, uint32_t addr) {
    asm volatile("ldmatrix.sync.aligned.m8n8.x4.shared.b16 {%0,%1,%2,%3}, [%4];"
                 : "=r"(r0), "=r"(r1), "=r"(r2), "=r"(r3) : "r"(addr));
}
__device__ __forceinline__ void mma_f16(float* c, const uint32_t* a,
                                        uint32_t b0, uint32_t b1) {
    asm volatile(
        "mma.sync.aligned.m16n8k16.row.col.f32.f16.f16.f32 "
        "{%0,%1,%2,%3},{%4,%5,%6,%7},{%8,%9},{%0,%1,%2,%3};"
        : "+f"(c[0]), "+f"(c[1]), "+f"(c[2]), "+f"(c[3])
        : "r"(a[0]), "r"(a[1]), "r"(a[2]), "r"(a[3]), "r"(b0), "r"(b1));
}
__device__ __forceinline__ void split_store2(__half* hp, __half* lp,
                                             float v0, float v1) {
    __half h0 = __float2half(v0), h1 = __float2half(v1);
    __half l0 = __float2half(v0 - __half2float(h0));
    __half l1 = __float2half(v1 - __half2float(h1));
    *(__half2*)hp = __halves2half2(h0, h1);
    *(__half2*)lp = __halves2half2(l0, l1);
}

/* =========================================================================
 * fp16x2 GEMM (mma.sync.m16n8k16):
 *   C[m,n] = epi( sum_k A[m,k]*B[n,k] + bias[n] )
 *   A ~ Ah+Al (fp16), B plain fp16.  acc += Ah*B + Al*B  (fp32 accum)
 * Tile 128x128, BK=32, cp.async double buffer, 256 threads, 2 CTAs/SM.
 * smem rows padded to 80B (bank-conflict-free ldmatrix/lds).
 * EPI: 0 = fp32 C = (acc+bias)*alpha
 *      1 = gelu_exact -> fp16 split (Ch, Cl), no fp32 output
 *      2 = fp32 C = acc + bias + r1 + r2
 * ========================================================================= */
#define TM 128
#define TN 128
#define BK 32
#define NCH (DIMC / BK)            /* 32 k-chunks */
#define PADB 80                    /* bytes per smem row (32 fp16 + pad) */
#define TILE_B (128 * PADB)        /* 10240 */
#define STAGE_B (3 * TILE_B)       /* Ah, Al, B */
#define GSMEM_DYN (2 * STAGE_B)    /* 61440 */

template<int EPI>
__global__ void __launch_bounds__(256, 2)
gemm_f16x2(const __half* __restrict__ Ah, const __half* __restrict__ Al,
           const __half* __restrict__ B,
           const float* __restrict__ bias, float* __restrict__ C,
           __half* __restrict__ Ch, __half* __restrict__ Cl,
           float alpha, const float* __restrict__ r1, const float* __restrict__ r2)
{
    extern __shared__ char smem[];
    const uint32_t sbase = smem_u32(smem);

    const int tid  = threadIdx.x;
    const int wid  = tid >> 5;
    const int lane = tid & 31;
    const int wm   = wid >> 2;     /* 0..1  -> 64-row slice  */
    const int wn   = wid & 3;      /* 0..3  -> 32-col slice  */
    const int g    = lane >> 2;    /* group 0..7 */
    const int t    = lane & 3;
    const int m0   = blockIdx.y * TM;
    const int n0   = blockIdx.x * TN;

    const char* srcs[3];
    srcs[0] = (const char*)(Ah + (size_t)m0 * DIMC);
    srcs[1] = (const char*)(Al + (size_t)m0 * DIMC);
    srcs[2] = (const char*)(B  + (size_t)n0 * DIMC);

    /* per-thread cp.async mapping: 6 x 16B chunks per stage (3 tiles) */
    int cid[6], crow[6], ccol[6];
#pragma unroll
    for (int it = 0; it < 6; it++) {
        int id = tid + it * 256;           /* 0..1535 */
        cid[it]  = id >> 9;                /* tile 0..2      */
        crow[it] = (id >> 2) & 127;        /* row 0..127     */
        ccol[it] = id & 3;                 /* 16B chunk 0..3 */
    }

    auto prefetch = [&](int ch, int buf) {
        const uint32_t sb = sbase + buf * STAGE_B;
#pragma unroll
        for (int it = 0; it < 6; it++) {
            const char* gp = srcs[cid[it]] + (size_t)crow[it] * (DIMC * 2)
                           + ch * (BK * 2) + ccol[it] * 16;
            uint32_t sa = sb + cid[it] * TILE_B + crow[it] * PADB + ccol[it] * 16;
            CP_ASYNC16(sa, gp);
        }
        CP_COMMIT();
    };

    float acc[4][4][4];
#pragma unroll
    for (int i = 0; i < 4; i++)
#pragma unroll
        for (int j = 0; j < 4; j++)
#pragma unroll
            for (int q = 0; q < 4; q++) acc[i][j][q] = 0.0f;

    prefetch(0, 0);

    const uint32_t lm_off = (uint32_t)(lane & 15) * PADB + (uint32_t)(lane >> 4) * 16;

    for (int ch = 0; ch < NCH; ch++) {
        const int buf = ch & 1;
        if (ch + 1 < NCH) { prefetch(ch + 1, buf ^ 1); CP_WAIT(1); }
        else              { CP_WAIT(0); }
        __syncthreads();

        const uint32_t sb  = sbase + buf * STAGE_B;
        const uint32_t aht = sb;
        const uint32_t alt = sb + TILE_B;
        const uint32_t bt  = sb + 2 * TILE_B;

#pragma unroll
        for (int ks = 0; ks < 2; ks++) {          /* two k16 steps per BK=32 */
            uint32_t bb[4][2];
#pragma unroll
            for (int j = 0; j < 4; j++) {
                uint32_t nrow = (uint32_t)(wn * 32 + j * 8 + g) * PADB + ks * 32 + t * 4;
                asm volatile("ld.shared.b32 %0, [%1];" : "=r"(bb[j][0]) : "r"(bt + nrow));
                asm volatile("ld.shared.b32 %0, [%1];" : "=r"(bb[j][1]) : "r"(bt + nrow + 16));
            }
#pragma unroll
            for (int i = 0; i < 4; i++) {
                uint32_t arow = (uint32_t)(wm * 64 + i * 16) * PADB + lm_off + ks * 32;
                uint32_t ah[4], al[4];
                ldsm_x4(ah[0], ah[1], ah[2], ah[3], aht + arow);
                ldsm_x4(al[0], al[1], al[2], al[3], alt + arow);
#pragma unroll
                for (int j = 0; j < 4; j++) {
                    mma_f16(acc[i][j], ah, bb[j][0], bb[j][1]);
                    mma_f16(acc[i][j], al, bb[j][0], bb[j][1]);
                }
            }
        }
        __syncthreads();
    }

    /* ---------------- epilogue: register-resident ---------------- */
#pragma unroll
    for (int i = 0; i < 4; i++) {
        const int row0 = m0 + wm * 64 + i * 16 + g;
#pragma unroll
        for (int j = 0; j < 4; j++) {
            const int col = n0 + wn * 32 + j * 8 + 2 * t;
            float2 b2 = *(const float2*)(bias + col);
            float v[4] = { acc[i][j][0] + b2.x, acc[i][j][1] + b2.y,
                           acc[i][j][2] + b2.x, acc[i][j][3] + b2.y };
            size_t p0 = (size_t)row0 * DIMC + col;
            size_t p1 = (size_t)(row0 + 8) * DIMC + col;
            if (EPI == 0) {
#pragma unroll
                for (int q = 0; q < 4; q++) v[q] *= alpha;
                *(float2*)(C + p0) = make_float2(v[0], v[1]);
                *(float2*)(C + p1) = make_float2(v[2], v[3]);
            } else if (EPI == 1) {
#pragma unroll
                for (int q = 0; q < 4; q++)
                    v[q] = 0.5f * v[q] * (1.0f + erff(v[q] * 0.70710678118654752f));
                split_store2(Ch + p0, Cl + p0, v[0], v[1]);
                split_store2(Ch + p1, Cl + p1, v[2], v[3]);
            } else {
                float2 x0 = *(const float2*)(r1 + p0), o0 = *(const float2*)(r2 + p0);
                float2 x1 = *(const float2*)(r1 + p1), o1 = *(const float2*)(r2 + p1);
                v[0] += x0.x + o0.x; v[1] += x0.y + o0.y;
                v[2] += x1.x + o1.x; v[3] += x1.y + o1.y;
                *(float2*)(C + p0) = make_float2(v[0], v[1]);
                *(float2*)(C + p1) = make_float2(v[2], v[3]);
            }
        }
    }
}

/* ================== fp32 -> fp16 (hi, lo) split ========================= */
__global__ void split_kernel(const float* __restrict__ in,
                             __half* __restrict__ hi,
                             __half* __restrict__ lo, int n)
{
    int i = (blockIdx.x * 256 + threadIdx.x) * 4;
    if (i >= n) return;
    float4 v = *(const float4*)(in + i);
    float f[4] = {v.x, v.y, v.z, v.w};
    __half h[4], l[4];
#pragma unroll
    for (int k = 0; k < 4; k++) {
        h[k] = __float2half(f[k]);
        l[k] = __float2half(f[k] - __half2float(h[k]));
    }
    *(__half2*)(hi + i)     = __halves2half2(h[0], h[1]);
    *(__half2*)(hi + i + 2) = __halves2half2(h[2], h[3]);
    *(__half2*)(lo + i)     = __halves2half2(l[0], l[1]);
    *(__half2*)(lo + i + 2) = __halves2half2(l[2], l[3]);
}

/* =========================================================================
 * Attention middle (exact fp32):  M_h = K_h^T V_h ;  OUT = Q_h @ M_h
 * ========================================================================= */
__global__ void __launch_bounds__(256)
kv_m_kernel(const float* __restrict__ K, const float* __restrict__ V,
            float* __restrict__ Mp)
{
    __shared__ float Ks[16][68];
    __shared__ float Vs[16][68];

    const int bh = blockIdx.x;               /* b*16 + h */
    const int b  = bh >> 4, h = bh & 15;
    const int s0 = blockIdx.y * 128;
    const int tid = threadIdx.x;
    const int e0 = (tid >> 4) * 4;
    const int d0 = (tid & 15) * 4;

    float acc[4][4] = {};
    const int lr = tid >> 4;
    const int lc = (tid & 15) * 4;

    for (int st = 0; st < 128; st += 16) {
        size_t gi = ((size_t)(b * SEQ + s0 + st + lr)) * DIMC + h * HD + lc;
        *(float4*)&Ks[lr][lc] = *(const float4*)(K + gi);
        *(float4*)&Vs[lr][lc] = *(const float4*)(V + gi);
        __syncthreads();
#pragma unroll
        for (int ss = 0; ss < 16; ss++) {
            float kv[4], vv[4];
#pragma unroll
            for (int i = 0; i < 4; i++) { kv[i] = Ks[ss][e0 + i]; vv[i] = Vs[ss][d0 + i]; }
#pragma unroll
            for (int i = 0; i < 4; i++)
#pragma unroll
                for (int jj = 0; jj < 4; jj++) acc[i][jj] += kv[i] * vv[jj];
        }
        __syncthreads();
    }

    float* mo = Mp + ((size_t)blockIdx.y * 32 + bh) * (HD * HD);
#pragma unroll
    for (int i = 0; i < 4; i++)
#pragma unroll
        for (int jj = 0; jj < 4; jj++)
            mo[(e0 + i) * HD + d0 + jj] = acc[i][jj];
}

__global__ void reduce_m_kernel(const float* __restrict__ Mp, float* __restrict__ Mo)
{
    int i = blockIdx.x * 256 + threadIdx.x;   /* 0 .. 32*4096-1 */
    float s = 0.0f;
#pragma unroll
    for (int p = 0; p < 16; p++) s += Mp[(size_t)p * 32 * HD * HD + i];
    Mo[i] = s;
}

/* OUT = Q @ M_h, fused fp16 split output for the MLP GEMM */
__global__ void __launch_bounds__(256)
qm_kernel(const float* __restrict__ Q, const float* __restrict__ Mi,
          float* __restrict__ O, __half* __restrict__ Oh, __half* __restrict__ Ol)
{
    __shared__ float Qs[64][68];
    __shared__ float Ms[64][68];

    const int bh = blockIdx.x;
    const int b  = bh >> 4, h = bh & 15;
    const int s0 = blockIdx.y * 64;
    const int tid = threadIdx.x;

#pragma unroll
    for (int p = 0; p < 4; p++) {
        int slot = tid + p * 256;
        int r = slot >> 4;
        int c = (slot & 15) * 4;
        *(float4*)&Qs[r][c] = *(const float4*)(Q + ((size_t)(b * SEQ + s0 + r)) * DIMC + h * HD + c);
        *(float4*)&Ms[r][c] = *(const float4*)(Mi + (size_t)bh * HD * HD + r * HD + c);
    }
    __syncthreads();

    const int r0 = (tid >> 4) * 4;
    const int c0 = (tid & 15) * 4;
    float acc[4][4] = {};
#pragma unroll
    for (int k = 0; k < 64; k++) {
        float qv[4], mv[4];
#pragma unroll
        for (int i = 0; i < 4; i++) qv[i] = Qs[r0 + i][k];
#pragma unroll
        for (int jj = 0; jj < 4; jj++) mv[jj] = Ms[k][c0 + jj];
#pragma unroll
        for (int i = 0; i < 4; i++)
#pragma unroll
            for (int jj = 0; jj < 4; jj++) acc[i][jj] += qv[i] * mv[jj];
    }
#pragma unroll
    for (int i = 0; i < 4; i++) {
        size_t base = ((size_t)(b * SEQ + s0 + r0 + i)) * DIMC + h * HD + c0;
#pragma unroll
        for (int jj = 0; jj < 4; jj++) O[base + jj] = acc[i][jj];
        split_store2(Oh + base,     Ol + base,     acc[i][0], acc[i][1]);
        split_store2(Oh + base + 2, Ol + base + 2, acc[i][2], acc[i][3]);
    }
}

/* ========================================================================= */
extern "C" void kernel_launch(void* const* d_in, const int* in_sizes, int n_in,
                              void* d_out, int out_size)
{
    const float* x  = (const float*)d_in[0];
    const float* Wq = (const float*)d_in[1];
    const float* bq = (const float*)d_in[2];
    const float* Wk = (const float*)d_in[3];
    const float* bk = (const float*)d_in[4];
    const float* Wv = (const float*)d_in[5];
    const float* bv = (const float*)d_in[6];
    const float* W1 = (const float*)d_in[7];
    const float* b1 = (const float*)d_in[8];
    const float* W2 = (const float*)d_in[9];
    const float* b2 = (const float*)d_in[10];
    float* Y = (float*)d_out;

    float *Q, *K, *V, *OUTP, *MP, *MM;
    cudaGetSymbolAddress((void**)&Q,    g_Q);
    cudaGetSymbolAddress((void**)&K,    g_K);
    cudaGetSymbolAddress((void**)&V,    g_V);
    cudaGetSymbolAddress((void**)&OUTP, g_OUT);
    cudaGetSymbolAddress((void**)&MP,   g_Mpart);
    cudaGetSymbolAddress((void**)&MM,   g_M);

    __half *xh, *xl, *oh, *ol, *hh, *hl;
    __half *wqh, *wql, *wkh, *wkl, *wvh, *wvl, *w1h, *w1l, *w2h, *w2l;
    cudaGetSymbolAddress((void**)&xh,  g_xh);  cudaGetSymbolAddress((void**)&xl,  g_xl);
    cudaGetSymbolAddress((void**)&oh,  g_oh);  cudaGetSymbolAddress((void**)&ol,  g_ol);
    cudaGetSymbolAddress((void**)&hh,  g_hh);  cudaGetSymbolAddress((void**)&hl,  g_hl);
    cudaGetSymbolAddress((void**)&wqh, g_wqh); cudaGetSymbolAddress((void**)&wql, g_wql);
    cudaGetSymbolAddress((void**)&wkh, g_wkh); cudaGetSymbolAddress((void**)&wkl, g_wkl);
    cudaGetSymbolAddress((void**)&wvh, g_wvh); cudaGetSymbolAddress((void**)&wvl, g_wvl);
    cudaGetSymbolAddress((void**)&w1h, g_w1h); cudaGetSymbolAddress((void**)&w1l, g_w1l);
    cudaGetSymbolAddress((void**)&w2h, g_w2h); cudaGetSymbolAddress((void**)&w2l, g_w2l);

    cudaFuncSetAttribute(gemm_f16x2<0>, cudaFuncAttributeMaxDynamicSharedMemorySize, GSMEM_DYN);
    cudaFuncSetAttribute(gemm_f16x2<1>, cudaFuncAttributeMaxDynamicSharedMemorySize, GSMEM_DYN);
    cudaFuncSetAttribute(gemm_f16x2<2>, cudaFuncAttributeMaxDynamicSharedMemorySize, GSMEM_DYN);

    const int NX = MTOT * DIMC;   /* 4.19M */
    const int NW = DIMC * DIMC;   /* 1.05M */
    dim3 sgx((NX / 4 + 255) / 256), sgw((NW / 4 + 255) / 256);

    /* fp16 splits of inputs (weights split-stored; only A-side uses lo) */
    split_kernel<<<sgx, 256>>>(x,  xh,  xl,  NX);
    split_kernel<<<sgw, 256>>>(Wq, wqh, wql, NW);
    split_kernel<<<sgw, 256>>>(Wk, wkh, wkl, NW);
    split_kernel<<<sgw, 256>>>(Wv, wvh, wvl, NW);
    split_kernel<<<sgw, 256>>>(W1, w1h, w1l, NW);
    split_kernel<<<sgw, 256>>>(W2, w2h, w2l, NW);

    dim3 ggrid(DIMC / TN, MTOT / TM);   /* (8, 32) */

    /* projections: A split fp16x2, B = hi part of weights */
    gemm_f16x2<0><<<ggrid, 256, GSMEM_DYN>>>(xh, xl, wqh, bq, Q, nullptr, nullptr, QSCALE, nullptr, nullptr);
    gemm_f16x2<0><<<ggrid, 256, GSMEM_DYN>>>(xh, xl, wkh, bk, K, nullptr, nullptr, 1.0f,   nullptr, nullptr);
    gemm_f16x2<0><<<ggrid, 256, GSMEM_DYN>>>(xh, xl, wvh, bv, V, nullptr, nullptr, 1.0f,   nullptr, nullptr);

    /* attention collapsed: out = Q @ (K^T V) per head, exact fp32 */
    kv_m_kernel<<<dim3(32, 16), 256>>>(K, V, MP);
    reduce_m_kernel<<<(32 * HD * HD) / 256, 256>>>(MP, MM);
    qm_kernel<<<dim3(32, SEQ / 64), 256>>>(Q, MM, OUTP, oh, ol);

    /* MLP: h = gelu(OUT @ W1^T + b1) -> fp16 split; Y = x + OUT + h @ W2^T + b2 */
    gemm_f16x2<1><<<ggrid, 256, GSMEM_DYN>>>(oh, ol, w1h, b1, nullptr, hh, hl, 1.0f, nullptr, nullptr);
    gemm_f16x2<2><<<ggrid, 256, GSMEM_DYN>>>(hh, hl, w2h, b2, Y, nullptr, nullptr, 1.0f, x, OUTP);
}

// round 13
// speedup vs baseline: 1.5420x; 1.1453x over previous
#include <cuda_runtime.h>
#include <cuda_fp16.h>
#include <math.h>
#include <stdint.h>

#define DIMC   1024
#define BATCH  2
#define SEQ    2048
#define MTOT   (BATCH*SEQ)      /* 4096 rows */
#define NHEAD  16
#define HD     64
#define QSCALE 0.125f           /* 64^-0.5 */

/* ------------------- scratch (allocations forbidden) ------------------- */
__device__ float g_Q  [MTOT * DIMC];
__device__ float g_K  [MTOT * DIMC];
__device__ float g_V  [MTOT * DIMC];
__device__ float g_OUT[MTOT * DIMC];
__device__ float g_Mpart[16 * BATCH * NHEAD * HD * HD];
__device__ float g_M  [BATCH * NHEAD * HD * HD];

/* fp16 operands */
__device__ __half g_xh [MTOT * DIMC], g_xl [MTOT * DIMC];
__device__ __half g_oh [MTOT * DIMC];
__device__ __half g_hh [MTOT * DIMC];
__device__ __half g_wqh[DIMC * DIMC];
__device__ __half g_wkh[DIMC * DIMC];
__device__ __half g_wvh[DIMC * DIMC];
__device__ __half g_w1h[DIMC * DIMC];
__device__ __half g_w2h[DIMC * DIMC];

/* ============================ asm helpers =============================== */
__device__ __forceinline__ uint32_t smem_u32(const void* p) {
    uint32_t a;
    asm("{ .reg .u64 t; cvta.to.shared.u64 t, %1; cvt.u32.u64 %0, t; }"
        : "=r"(a) : "l"(p));
    return a;
}
#define CP_ASYNC16(saddr, gptr) \
    asm volatile("cp.async.cg.shared.global [%0], [%1], 16;" \
                 :: "r"(saddr), "l"(gptr) : "memory")
#define CP_COMMIT()  asm volatile("cp.async.commit_group;" ::: "memory")
#define CP_WAIT(N)   asm volatile("cp.async.wait_group %0;" :: "n"(N) : "memory")

__device__ __forceinline__ void ldsm_x4(uint32_t& r0, uint32_t& r1,
                                        uint32_t& r2, uint32_t& r3, uint32_t addr) {
    asm volatile("ldmatrix.sync.aligned.m8n8.x4.shared.b16 {%0,%1,%2,%3}, [%4];"
                 : "=r"(r0), "=r"(r1), "=r"(r2), "=r"(r3) : "r"(addr));
}
__device__ __forceinline__ void mma_f16(float* c, const uint32_t* a,
                                        uint32_t b0, uint32_t b1) {
    asm volatile(
        "mma.sync.aligned.m16n8k16.row.col.f32.f16.f16.f32 "
        "{%0,%1,%2,%3},{%4,%5,%6,%7},{%8,%9},{%0,%1,%2,%3};"
        : "+f"(c[0]), "+f"(c[1]), "+f"(c[2]), "+f"(c[3])
        : "r"(a[0]), "r"(a[1]), "r"(a[2]), "r"(a[3]), "r"(b0), "r"(b1));
}

/* =========================================================================
 * fp16 GEMM (mma.sync.m16n8k16):
 *   C[m,n] = epi( sum_k A[m,k]*B[n,k] + bias[n] )
 * SPLIT=1: A ~ Ah+Al (fp16), acc += Ah*B + Al*B  (2 MMAs)
 * SPLIT=0: A plain fp16 (1 MMA)
 * Tile 128x128, BK=32, 3-stage cp.async pipeline, one sync per chunk,
 * 256 threads, 2 CTAs/SM. smem rows padded to 80B.
 * EPI: 0 = fp32 C = (acc+bias)*alpha
 *      1 = gelu_exact -> fp16 C (Ch)
 *      2 = fp32 C = acc + bias + r1 + r2
 * ========================================================================= */
#define TM 128
#define TN 128
#define BK 32
#define NCH (DIMC / BK)            /* 32 k-chunks */
#define PADB 80                    /* bytes per smem row (32 fp16 + pad) */
#define TILE_B (128 * PADB)        /* 10240 */
#define NSTAGE 3

template<int SPLIT, int EPI>
__global__ void __launch_bounds__(256, 2)
gemm_f16(const __half* __restrict__ Ah, const __half* __restrict__ Al,
         const __half* __restrict__ B,
         const float* __restrict__ bias, float* __restrict__ C,
         __half* __restrict__ Ch,
         float alpha, const float* __restrict__ r1, const float* __restrict__ r2)
{
    constexpr int NT    = SPLIT ? 3 : 2;     /* tiles per stage          */
    constexpr int STB   = NT * TILE_B;       /* bytes per stage          */
    constexpr int NCK   = NT * 2;            /* 16B chunks per thread    */

    extern __shared__ char smem[];
    const uint32_t sbase = smem_u32(smem);

    const int tid  = threadIdx.x;
    const int wid  = tid >> 5;
    const int lane = tid & 31;
    const int wm   = wid >> 2;     /* 0..1  -> 64-row slice  */
    const int wn   = wid & 3;      /* 0..3  -> 32-col slice  */
    const int g    = lane >> 2;    /* group 0..7 */
    const int t    = lane & 3;
    const int m0   = blockIdx.y * TM;
    const int n0   = blockIdx.x * TN;

    const char* srcs[NT];
    srcs[0] = (const char*)(Ah + (size_t)m0 * DIMC);
    if (SPLIT) {
        srcs[1] = (const char*)(Al + (size_t)m0 * DIMC);
        srcs[2] = (const char*)(B  + (size_t)n0 * DIMC);
    } else {
        srcs[1] = (const char*)(B  + (size_t)n0 * DIMC);
    }

    int cid[NCK], crow[NCK], ccol[NCK];
#pragma unroll
    for (int it = 0; it < NCK; it++) {
        int id = tid + it * 256;
        cid[it]  = id >> 9;                /* tile            */
        crow[it] = (id >> 2) & 127;        /* row 0..127      */
        ccol[it] = id & 3;                 /* 16B chunk 0..3  */
    }

    auto prefetch = [&](int ch, int buf) {
        const uint32_t sb = sbase + buf * STB;
#pragma unroll
        for (int it = 0; it < NCK; it++) {
            const char* gp = srcs[cid[it]] + (size_t)crow[it] * (DIMC * 2)
                           + ch * (BK * 2) + ccol[it] * 16;
            uint32_t sa = sb + cid[it] * TILE_B + crow[it] * PADB + ccol[it] * 16;
            CP_ASYNC16(sa, gp);
        }
        CP_COMMIT();
    };

    float acc[4][4][4];
#pragma unroll
    for (int i = 0; i < 4; i++)
#pragma unroll
        for (int j = 0; j < 4; j++)
#pragma unroll
            for (int q = 0; q < 4; q++) acc[i][j][q] = 0.0f;

    prefetch(0, 0);
    prefetch(1, 1);

    const uint32_t lm_off = (uint32_t)(lane & 15) * PADB + (uint32_t)(lane >> 4) * 16;

    int bufc = 0;
    for (int ch = 0; ch < NCH; ch++) {
        if (ch + 1 < NCH) { CP_WAIT(1); } else { CP_WAIT(0); }
        __syncthreads();

        /* prefetch 2 chunks ahead into the buffer freed last iteration */
        if (ch + 2 < NCH) {
            int pf = bufc + 2; if (pf >= NSTAGE) pf -= NSTAGE;
            prefetch(ch + 2, pf);
        }

        const uint32_t sb  = sbase + bufc * STB;
        const uint32_t aht = sb;
        const uint32_t alt = sb + TILE_B;                 /* SPLIT only */
        const uint32_t bt  = sb + (NT - 1) * TILE_B;

#pragma unroll
        for (int ks = 0; ks < 2; ks++) {          /* two k16 steps per BK=32 */
            uint32_t bb[4][2];
#pragma unroll
            for (int j = 0; j < 4; j++) {
                uint32_t nrow = (uint32_t)(wn * 32 + j * 8 + g) * PADB + ks * 32 + t * 4;
                asm volatile("ld.shared.b32 %0, [%1];" : "=r"(bb[j][0]) : "r"(bt + nrow));
                asm volatile("ld.shared.b32 %0, [%1];" : "=r"(bb[j][1]) : "r"(bt + nrow + 16));
            }
#pragma unroll
            for (int i = 0; i < 4; i++) {
                uint32_t arow = (uint32_t)(wm * 64 + i * 16) * PADB + lm_off + ks * 32;
                uint32_t ah[4], al[4];
                ldsm_x4(ah[0], ah[1], ah[2], ah[3], aht + arow);
                if (SPLIT) ldsm_x4(al[0], al[1], al[2], al[3], alt + arow);
#pragma unroll
                for (int j = 0; j < 4; j++) {
                    mma_f16(acc[i][j], ah, bb[j][0], bb[j][1]);
                    if (SPLIT) mma_f16(acc[i][j], al, bb[j][0], bb[j][1]);
                }
            }
        }
        bufc = (bufc + 1 == NSTAGE) ? 0 : bufc + 1;
    }

    /* ---------------- epilogue: register-resident ---------------- */
#pragma unroll
    for (int i = 0; i < 4; i++) {
        const int row0 = m0 + wm * 64 + i * 16 + g;
#pragma unroll
        for (int j = 0; j < 4; j++) {
            const int col = n0 + wn * 32 + j * 8 + 2 * t;
            float2 b2 = *(const float2*)(bias + col);
            float v[4] = { acc[i][j][0] + b2.x, acc[i][j][1] + b2.y,
                           acc[i][j][2] + b2.x, acc[i][j][3] + b2.y };
            size_t p0 = (size_t)row0 * DIMC + col;
            size_t p1 = (size_t)(row0 + 8) * DIMC + col;
            if (EPI == 0) {
#pragma unroll
                for (int q = 0; q < 4; q++) v[q] *= alpha;
                *(float2*)(C + p0) = make_float2(v[0], v[1]);
                *(float2*)(C + p1) = make_float2(v[2], v[3]);
            } else if (EPI == 1) {
#pragma unroll
                for (int q = 0; q < 4; q++)
                    v[q] = 0.5f * v[q] * (1.0f + erff(v[q] * 0.70710678118654752f));
                *(__half2*)(Ch + p0) = __halves2half2(__float2half(v[0]), __float2half(v[1]));
                *(__half2*)(Ch + p1) = __halves2half2(__float2half(v[2]), __float2half(v[3]));
            } else {
                float2 x0 = *(const float2*)(r1 + p0), o0 = *(const float2*)(r2 + p0);
                float2 x1 = *(const float2*)(r1 + p1), o1 = *(const float2*)(r2 + p1);
                v[0] += x0.x + o0.x; v[1] += x0.y + o0.y;
                v[2] += x1.x + o1.x; v[3] += x1.y + o1.y;
                *(float2*)(C + p0) = make_float2(v[0], v[1]);
                *(float2*)(C + p1) = make_float2(v[2], v[3]);
            }
        }
    }
}

#define GSMEM_S1 (NSTAGE * 3 * TILE_B)   /* 92160 */
#define GSMEM_S0 (NSTAGE * 2 * TILE_B)   /* 61440 */

/* ================== fp32 -> fp16 (hi, lo) split ========================= */
__global__ void split_kernel(const float* __restrict__ in,
                             __half* __restrict__ hi,
                             __half* __restrict__ lo, int n)
{
    int i = (blockIdx.x * 256 + threadIdx.x) * 4;
    if (i >= n) return;
    float4 v = *(const float4*)(in + i);
    float f[4] = {v.x, v.y, v.z, v.w};
    __half h[4], l[4];
#pragma unroll
    for (int k = 0; k < 4; k++) {
        h[k] = __float2half(f[k]);
        l[k] = __float2half(f[k] - __half2float(h[k]));
    }
    *(__half2*)(hi + i)     = __halves2half2(h[0], h[1]);
    *(__half2*)(hi + i + 2) = __halves2half2(h[2], h[3]);
    *(__half2*)(lo + i)     = __halves2half2(l[0], l[1]);
    *(__half2*)(lo + i + 2) = __halves2half2(l[2], l[3]);
}

/* fp32 -> fp16 (hi only) for weights */
__global__ void tohalf_kernel(const float* __restrict__ in,
                              __half* __restrict__ hi, int n)
{
    int i = (blockIdx.x * 256 + threadIdx.x) * 4;
    if (i >= n) return;
    float4 v = *(const float4*)(in + i);
    *(__half2*)(hi + i)     = __halves2half2(__float2half(v.x), __float2half(v.y));
    *(__half2*)(hi + i + 2) = __halves2half2(__float2half(v.z), __float2half(v.w));
}

/* =========================================================================
 * Attention middle (exact fp32):  M_h = K_h^T V_h ;  OUT = Q_h @ M_h
 * ========================================================================= */
__global__ void __launch_bounds__(256)
kv_m_kernel(const float* __restrict__ K, const float* __restrict__ V,
            float* __restrict__ Mp)
{
    __shared__ float Ks[16][68];
    __shared__ float Vs[16][68];

    const int bh = blockIdx.x;               /* b*16 + h */
    const int b  = bh >> 4, h = bh & 15;
    const int s0 = blockIdx.y * 128;
    const int tid = threadIdx.x;
    const int e0 = (tid >> 4) * 4;
    const int d0 = (tid & 15) * 4;

    float acc[4][4] = {};
    const int lr = tid >> 4;
    const int lc = (tid & 15) * 4;

    for (int st = 0; st < 128; st += 16) {
        size_t gi = ((size_t)(b * SEQ + s0 + st + lr)) * DIMC + h * HD + lc;
        *(float4*)&Ks[lr][lc] = *(const float4*)(K + gi);
        *(float4*)&Vs[lr][lc] = *(const float4*)(V + gi);
        __syncthreads();
#pragma unroll
        for (int ss = 0; ss < 16; ss++) {
            float kv[4], vv[4];
#pragma unroll
            for (int i = 0; i < 4; i++) { kv[i] = Ks[ss][e0 + i]; vv[i] = Vs[ss][d0 + i]; }
#pragma unroll
            for (int i = 0; i < 4; i++)
#pragma unroll
                for (int jj = 0; jj < 4; jj++) acc[i][jj] += kv[i] * vv[jj];
        }
        __syncthreads();
    }

    float* mo = Mp + ((size_t)blockIdx.y * 32 + bh) * (HD * HD);
#pragma unroll
    for (int i = 0; i < 4; i++)
#pragma unroll
        for (int jj = 0; jj < 4; jj++)
            mo[(e0 + i) * HD + d0 + jj] = acc[i][jj];
}

__global__ void reduce_m_kernel(const float* __restrict__ Mp, float* __restrict__ Mo)
{
    int i = blockIdx.x * 256 + threadIdx.x;   /* 0 .. 32*4096-1 */
    float s = 0.0f;
#pragma unroll
    for (int p = 0; p < 16; p++) s += Mp[(size_t)p * 32 * HD * HD + i];
    Mo[i] = s;
}

/* OUT = Q @ M_h, fused fp16 output for the MLP GEMM */
__global__ void __launch_bounds__(256)
qm_kernel(const float* __restrict__ Q, const float* __restrict__ Mi,
          float* __restrict__ O, __half* __restrict__ Oh)
{
    __shared__ float Qs[64][68];
    __shared__ float Ms[64][68];

    const int bh = blockIdx.x;
    const int b  = bh >> 4, h = bh & 15;
    const int s0 = blockIdx.y * 64;
    const int tid = threadIdx.x;

#pragma unroll
    for (int p = 0; p < 4; p++) {
        int slot = tid + p * 256;
        int r = slot >> 4;
        int c = (slot & 15) * 4;
        *(float4*)&Qs[r][c] = *(const float4*)(Q + ((size_t)(b * SEQ + s0 + r)) * DIMC + h * HD + c);
        *(float4*)&Ms[r][c] = *(const float4*)(Mi + (size_t)bh * HD * HD + r * HD + c);
    }
    __syncthreads();

    const int r0 = (tid >> 4) * 4;
    const int c0 = (tid & 15) * 4;
    float acc[4][4] = {};
#pragma unroll
    for (int k = 0; k < 64; k++) {
        float qv[4], mv[4];
#pragma unroll
        for (int i = 0; i < 4; i++) qv[i] = Qs[r0 + i][k];
#pragma unroll
        for (int jj = 0; jj < 4; jj++) mv[jj] = Ms[k][c0 + jj];
#pragma unroll
        for (int i = 0; i < 4; i++)
#pragma unroll
            for (int jj = 0; jj < 4; jj++) acc[i][jj] += qv[i] * mv[jj];
    }
#pragma unroll
    for (int i = 0; i < 4; i++) {
        size_t base = ((size_t)(b * SEQ + s0 + r0 + i)) * DIMC + h * HD + c0;
#pragma unroll
        for (int jj = 0; jj < 4; jj++) O[base + jj] = acc[i][jj];
        *(__half2*)(Oh + base)     = __halves2half2(__float2half(acc[i][0]), __float2half(acc[i][1]));
        *(__half2*)(Oh + base + 2) = __halves2half2(__float2half(acc[i][2]), __float2half(acc[i][3]));
    }
}

/* ========================================================================= */
extern "C" void kernel_launch(void* const* d_in, const int* in_sizes, int n_in,
                              void* d_out, int out_size)
{
    const float* x  = (const float*)d_in[0];
    const float* Wq = (const float*)d_in[1];
    const float* bq = (const float*)d_in[2];
    const float* Wk = (const float*)d_in[3];
    const float* bk = (const float*)d_in[4];
    const float* Wv = (const float*)d_in[5];
    const float* bv = (const float*)d_in[6];
    const float* W1 = (const float*)d_in[7];
    const float* b1 = (const float*)d_in[8];
    const float* W2 = (const float*)d_in[9];
    const float* b2 = (const float*)d_in[10];
    float* Y = (float*)d_out;

    float *Q, *K, *V, *OUTP, *MP, *MM;
    cudaGetSymbolAddress((void**)&Q,    g_Q);
    cudaGetSymbolAddress((void**)&K,    g_K);
    cudaGetSymbolAddress((void**)&V,    g_V);
    cudaGetSymbolAddress((void**)&OUTP, g_OUT);
    cudaGetSymbolAddress((void**)&MP,   g_Mpart);
    cudaGetSymbolAddress((void**)&MM,   g_M);

    __half *xh, *xl, *oh, *hh, *wqh, *wkh, *wvh, *w1h, *w2h;
    cudaGetSymbolAddress((void**)&xh,  g_xh);  cudaGetSymbolAddress((void**)&xl,  g_xl);
    cudaGetSymbolAddress((void**)&oh,  g_oh);
    cudaGetSymbolAddress((void**)&hh,  g_hh);
    cudaGetSymbolAddress((void**)&wqh, g_wqh);
    cudaGetSymbolAddress((void**)&wkh, g_wkh);
    cudaGetSymbolAddress((void**)&wvh, g_wvh);
    cudaGetSymbolAddress((void**)&w1h, g_w1h);
    cudaGetSymbolAddress((void**)&w2h, g_w2h);

    cudaFuncSetAttribute(gemm_f16<1,0>, cudaFuncAttributeMaxDynamicSharedMemorySize, GSMEM_S1);
    cudaFuncSetAttribute(gemm_f16<0,1>, cudaFuncAttributeMaxDynamicSharedMemorySize, GSMEM_S0);
    cudaFuncSetAttribute(gemm_f16<0,2>, cudaFuncAttributeMaxDynamicSharedMemorySize, GSMEM_S0);

    const int NX = MTOT * DIMC;   /* 4.19M */
    const int NW = DIMC * DIMC;   /* 1.05M */
    dim3 sgx((NX / 4 + 255) / 256), sgw((NW / 4 + 255) / 256);

    /* x split (hi+lo); weights hi-only */
    split_kernel <<<sgx, 256>>>(x,  xh, xl, NX);
    tohalf_kernel<<<sgw, 256>>>(Wq, wqh, NW);
    tohalf_kernel<<<sgw, 256>>>(Wk, wkh, NW);
    tohalf_kernel<<<sgw, 256>>>(Wv, wvh, NW);
    tohalf_kernel<<<sgw, 256>>>(W1, w1h, NW);
    tohalf_kernel<<<sgw, 256>>>(W2, w2h, NW);

    dim3 ggrid(DIMC / TN, MTOT / TM);   /* (8, 32) */

    /* projections: A split fp16x2 (2 MMAs), B plain fp16 */
    gemm_f16<1,0><<<ggrid, 256, GSMEM_S1>>>(xh, xl, wqh, bq, Q, nullptr, QSCALE, nullptr, nullptr);
    gemm_f16<1,0><<<ggrid, 256, GSMEM_S1>>>(xh, xl, wkh, bk, K, nullptr, 1.0f,   nullptr, nullptr);
    gemm_f16<1,0><<<ggrid, 256, GSMEM_S1>>>(xh, xl, wvh, bv, V, nullptr, 1.0f,   nullptr, nullptr);

    /* attention collapsed: out = Q @ (K^T V) per head, exact fp32 */
    kv_m_kernel<<<dim3(32, 16), 256>>>(K, V, MP);
    reduce_m_kernel<<<(32 * HD * HD) / 256, 256>>>(MP, MM);
    qm_kernel<<<dim3(32, SEQ / 64), 256>>>(Q, MM, OUTP, oh);

    /* MLP (plain fp16, 1 MMA — small branch relative to Y):
       h = gelu(OUT @ W1^T + b1) -> fp16; Y = x + OUT + h @ W2^T + b2 */
    gemm_f16<0,1><<<ggrid, 256, GSMEM_S0>>>(oh, nullptr, w1h, b1, nullptr, hh, 1.0f, nullptr, nullptr);
    gemm_f16<0,2><<<ggrid, 256, GSMEM_S0>>>(hh, nullptr, w2h, b2, Y, nullptr, 1.0f, x, OUTP);
}

// round 14
// speedup vs baseline: 1.6660x; 1.0804x over previous
#include <cuda_runtime.h>
#include <cuda_fp16.h>
#include <math.h>
#include <stdint.h>

#define DIMC   1024
#define BATCH  2
#define SEQ    2048
#define MTOT   (BATCH*SEQ)      /* 4096 rows */
#define NHEAD  16
#define HD     64
#define QSCALE 0.125f           /* 64^-0.5 */

/* ------------------- scratch (allocations forbidden) ------------------- */
__device__ float g_Q  [MTOT * DIMC];
__device__ float g_K  [MTOT * DIMC];
__device__ float g_V  [MTOT * DIMC];
__device__ float g_OUT[MTOT * DIMC];
__device__ float g_Mpart[16 * BATCH * NHEAD * HD * HD];
__device__ float g_M  [BATCH * NHEAD * HD * HD];

/* fp16 operands */
__device__ __half g_xh  [MTOT * DIMC], g_xl[MTOT * DIMC];
__device__ __half g_oh  [MTOT * DIMC];
__device__ __half g_hh  [MTOT * DIMC];
__device__ __half g_wqkv[3 * DIMC * DIMC];    /* Wq | Wk | Wv  (fp16) */
__device__ __half g_w1h [DIMC * DIMC];
__device__ __half g_w2h [DIMC * DIMC];

/* ============================ asm helpers =============================== */
__device__ __forceinline__ uint32_t smem_u32(const void* p) {
    uint32_t a;
    asm("{ .reg .u64 t; cvta.to.shared.u64 t, %1; cvt.u32.u64 %0, t; }"
        : "=r"(a) : "l"(p));
    return a;
}
#define CP_ASYNC16(saddr, gptr) \
    asm volatile("cp.async.cg.shared.global [%0], [%1], 16;" \
                 :: "r"(saddr), "l"(gptr) : "memory")
#define CP_COMMIT()  asm volatile("cp.async.commit_group;" ::: "memory")
#define CP_WAIT(N)   asm volatile("cp.async.wait_group %0;" :: "n"(N) : "memory")

__device__ __forceinline__ void ldsm_x4(uint32_t& r0, uint32_t& r1,
                                        uint32_t& r2, uint32_t& r3, uint32_t addr) {
    asm volatile("ldmatrix.sync.aligned.m8n8.x4.shared.b16 {%0,%1,%2,%3}, [%4];"
                 : "=r"(r0), "=r"(r1), "=r"(r2), "=r"(r3) : "r"(addr));
}
__device__ __forceinline__ void mma_f16(float* c, const uint32_t* a,
                                        uint32_t b0, uint32_t b1) {
    asm volatile(
        "mma.sync.aligned.m16n8k16.row.col.f32.f16.f16.f32 "
        "{%0,%1,%2,%3},{%4,%5,%6,%7},{%8,%9},{%0,%1,%2,%3};"
        : "+f"(c[0]), "+f"(c[1]), "+f"(c[2]), "+f"(c[3])
        : "r"(a[0]), "r"(a[1]), "r"(a[2]), "r"(a[3]), "r"(b0), "r"(b1));
}

/* =========================================================================
 * fp16 GEMM (mma.sync.m16n8k16):
 *   C[m,n] = epi( sum_k A[m,k]*B[n,k] + bias[n] )
 * SPLIT=1: A ~ Ah+Al (fp16), acc += Ah*B + Al*B  (2 MMAs)
 * CTA tile 128x128, warptile 64x64 (4 warps, 128 threads), 2 CTAs/SM,
 * BK=32, 3-stage cp.async pipeline, one sync per chunk, 80B-padded smem rows.
 * EPI: 1 = gelu_exact -> fp16 Ch
 *      2 = fp32 C = acc + bias + r1 + r2
 *      3 = fused QKV: route by column range (Q gets *QSCALE), fp32 out
 * ========================================================================= */
#define TM 128
#define TN 128
#define BK 32
#define NCH (DIMC / BK)            /* 32 k-chunks */
#define PADB 80                    /* bytes per smem row (32 fp16 + pad) */
#define TILE_B (128 * PADB)        /* 10240 */
#define NSTAGE 3
#define NTHR 128

template<int SPLIT, int EPI>
__global__ void __launch_bounds__(NTHR, 2)
gemm_f16(const __half* __restrict__ Ah, const __half* __restrict__ Al,
         const __half* __restrict__ B,
         const float* __restrict__ bias, float* __restrict__ C,
         __half* __restrict__ Ch,
         const float* __restrict__ r1, const float* __restrict__ r2,
         float* __restrict__ CK, float* __restrict__ CV,
         const float* __restrict__ bk, const float* __restrict__ bv)
{
    constexpr int NT  = SPLIT ? 3 : 2;     /* tiles per stage            */
    constexpr int STB = NT * TILE_B;       /* bytes per stage            */
    constexpr int NCK = NT * 4;            /* 16B chunks per thread      */

    extern __shared__ char smem[];
    const uint32_t sbase = smem_u32(smem);

    const int tid  = threadIdx.x;
    const int wid  = tid >> 5;
    const int lane = tid & 31;
    const int wm   = wid >> 1;     /* 0..1 : 64-row slice */
    const int wn   = wid & 1;      /* 0..1 : 64-col slice */
    const int g    = lane >> 2;    /* 0..7 */
    const int t    = lane & 3;
    const int m0   = blockIdx.y * TM;
    const int n0   = blockIdx.x * TN;      /* EPI==3: column in 0..3071 */

    const char* srcs[NT];
    srcs[0] = (const char*)(Ah + (size_t)m0 * DIMC);
    if (SPLIT) {
        srcs[1] = (const char*)(Al + (size_t)m0 * DIMC);
        srcs[2] = (const char*)(B  + (size_t)n0 * DIMC);
    } else {
        srcs[1] = (const char*)(B  + (size_t)n0 * DIMC);
    }

    int cid[NCK], crow[NCK], ccol[NCK];
#pragma unroll
    for (int it = 0; it < NCK; it++) {
        int id = tid + it * NTHR;
        cid[it]  = id >> 9;                /* tile            */
        crow[it] = (id >> 2) & 127;        /* row 0..127      */
        ccol[it] = id & 3;                 /* 16B chunk 0..3  */
    }

    auto prefetch = [&](int ch, int buf) {
        const uint32_t sb = sbase + buf * STB;
#pragma unroll
        for (int it = 0; it < NCK; it++) {
            const char* gp = srcs[cid[it]] + (size_t)crow[it] * (DIMC * 2)
                           + ch * (BK * 2) + ccol[it] * 16;
            uint32_t sa = sb + cid[it] * TILE_B + crow[it] * PADB + ccol[it] * 16;
            CP_ASYNC16(sa, gp);
        }
        CP_COMMIT();
    };

    float acc[4][8][4];
#pragma unroll
    for (int i = 0; i < 4; i++)
#pragma unroll
        for (int j = 0; j < 8; j++)
#pragma unroll
            for (int q = 0; q < 4; q++) acc[i][j][q] = 0.0f;

    prefetch(0, 0);
    prefetch(1, 1);

    const uint32_t lm_off = (uint32_t)(lane & 15) * PADB + (uint32_t)(lane >> 4) * 16;

    int bufc = 0;
    for (int ch = 0; ch < NCH; ch++) {
        if (ch + 1 < NCH) { CP_WAIT(1); } else { CP_WAIT(0); }
        __syncthreads();

        if (ch + 2 < NCH) {
            int pf = bufc + 2; if (pf >= NSTAGE) pf -= NSTAGE;
            prefetch(ch + 2, pf);
        }

        const uint32_t sb  = sbase + bufc * STB;
        const uint32_t aht = sb;
        const uint32_t alt = sb + TILE_B;                 /* SPLIT only */
        const uint32_t bt  = sb + (NT - 1) * TILE_B;

#pragma unroll
        for (int ks = 0; ks < 2; ks++) {          /* two k16 steps per BK=32 */
            uint32_t bb[8][2];
#pragma unroll
            for (int j = 0; j < 8; j++) {
                uint32_t nrow = (uint32_t)(wn * 64 + j * 8 + g) * PADB + ks * 32 + t * 4;
                asm volatile("ld.shared.b32 %0, [%1];" : "=r"(bb[j][0]) : "r"(bt + nrow));
                asm volatile("ld.shared.b32 %0, [%1];" : "=r"(bb[j][1]) : "r"(bt + nrow + 16));
            }
#pragma unroll
            for (int i = 0; i < 4; i++) {
                uint32_t arow = (uint32_t)(wm * 64 + i * 16) * PADB + lm_off + ks * 32;
                uint32_t ah[4], al[4];
                ldsm_x4(ah[0], ah[1], ah[2], ah[3], aht + arow);
                if (SPLIT) ldsm_x4(al[0], al[1], al[2], al[3], alt + arow);
#pragma unroll
                for (int j = 0; j < 8; j++) {
                    mma_f16(acc[i][j], ah, bb[j][0], bb[j][1]);
                    if (SPLIT) mma_f16(acc[i][j], al, bb[j][0], bb[j][1]);
                }
            }
        }
        bufc = (bufc + 1 == NSTAGE) ? 0 : bufc + 1;
    }

    /* ---------------- epilogue: register-resident ---------------- */
    /* EPI==3: select output slice (Q/K/V) by global column range */
    const int which = (EPI == 3) ? (n0 >> 10) : 0;
    const float* bs = bias;
    float* Cw = C;
    float alpha = 1.0f;
    if (EPI == 3) {
        if (which == 1)      { bs = bk; Cw = CK; }
        else if (which == 2) { bs = bv; Cw = CV; }
        else                 { alpha = QSCALE; }
    }
    const int ncol0 = (EPI == 3) ? (n0 & 1023) : n0;

#pragma unroll
    for (int i = 0; i < 4; i++) {
        const int row0 = m0 + wm * 64 + i * 16 + g;
#pragma unroll
        for (int j = 0; j < 8; j++) {
            const int col = ncol0 + wn * 64 + j * 8 + 2 * t;
            float2 b2 = *(const float2*)(bs + col);
            float v[4] = { acc[i][j][0] + b2.x, acc[i][j][1] + b2.y,
                           acc[i][j][2] + b2.x, acc[i][j][3] + b2.y };
            size_t p0 = (size_t)row0 * DIMC + col;
            size_t p1 = (size_t)(row0 + 8) * DIMC + col;
            if (EPI == 3) {
#pragma unroll
                for (int q = 0; q < 4; q++) v[q] *= alpha;
                *(float2*)(Cw + p0) = make_float2(v[0], v[1]);
                *(float2*)(Cw + p1) = make_float2(v[2], v[3]);
            } else if (EPI == 1) {
#pragma unroll
                for (int q = 0; q < 4; q++)
                    v[q] = 0.5f * v[q] * (1.0f + erff(v[q] * 0.70710678118654752f));
                *(__half2*)(Ch + p0) = __halves2half2(__float2half(v[0]), __float2half(v[1]));
                *(__half2*)(Ch + p1) = __halves2half2(__float2half(v[2]), __float2half(v[3]));
            } else {   /* EPI == 2 */
                float2 x0 = *(const float2*)(r1 + p0), o0 = *(const float2*)(r2 + p0);
                float2 x1 = *(const float2*)(r1 + p1), o1 = *(const float2*)(r2 + p1);
                v[0] += x0.x + o0.x; v[1] += x0.y + o0.y;
                v[2] += x1.x + o1.x; v[3] += x1.y + o1.y;
                *(float2*)(Cw + p0) = make_float2(v[0], v[1]);
                *(float2*)(Cw + p1) = make_float2(v[2], v[3]);
            }
        }
    }
}

#define GSMEM_S1 (NSTAGE * 3 * TILE_B)   /* 92160 */
#define GSMEM_S0 (NSTAGE * 2 * TILE_B)   /* 61440 */

/* ================== fp32 -> fp16 (hi, lo) split ========================= */
__global__ void split_kernel(const float* __restrict__ in,
                             __half* __restrict__ hi,
                             __half* __restrict__ lo, int n)
{
    int i = (blockIdx.x * 256 + threadIdx.x) * 4;
    if (i >= n) return;
    float4 v = *(const float4*)(in + i);
    float f[4] = {v.x, v.y, v.z, v.w};
    __half h[4], l[4];
#pragma unroll
    for (int k = 0; k < 4; k++) {
        h[k] = __float2half(f[k]);
        l[k] = __float2half(f[k] - __half2float(h[k]));
    }
    *(__half2*)(hi + i)     = __halves2half2(h[0], h[1]);
    *(__half2*)(hi + i + 2) = __halves2half2(h[2], h[3]);
    *(__half2*)(lo + i)     = __halves2half2(l[0], l[1]);
    *(__half2*)(lo + i + 2) = __halves2half2(l[2], l[3]);
}

/* fp32 -> fp16 (hi only) for weights */
__global__ void tohalf_kernel(const float* __restrict__ in,
                              __half* __restrict__ hi, int n)
{
    int i = (blockIdx.x * 256 + threadIdx.x) * 4;
    if (i >= n) return;
    float4 v = *(const float4*)(in + i);
    *(__half2*)(hi + i)     = __halves2half2(__float2half(v.x), __float2half(v.y));
    *(__half2*)(hi + i + 2) = __halves2half2(__float2half(v.z), __float2half(v.w));
}

/* =========================================================================
 * Attention middle (exact fp32):  M_h = K_h^T V_h ;  OUT = Q_h @ M_h
 * ========================================================================= */
__global__ void __launch_bounds__(256)
kv_m_kernel(const float* __restrict__ K, const float* __restrict__ V,
            float* __restrict__ Mp)
{
    __shared__ float Ks[16][68];
    __shared__ float Vs[16][68];

    const int bh = blockIdx.x;               /* b*16 + h */
    const int b  = bh >> 4, h = bh & 15;
    const int s0 = blockIdx.y * 128;
    const int tid = threadIdx.x;
    const int e0 = (tid >> 4) * 4;
    const int d0 = (tid & 15) * 4;

    float acc[4][4] = {};
    const int lr = tid >> 4;
    const int lc = (tid & 15) * 4;

    for (int st = 0; st < 128; st += 16) {
        size_t gi = ((size_t)(b * SEQ + s0 + st + lr)) * DIMC + h * HD + lc;
        *(float4*)&Ks[lr][lc] = *(const float4*)(K + gi);
        *(float4*)&Vs[lr][lc] = *(const float4*)(V + gi);
        __syncthreads();
#pragma unroll
        for (int ss = 0; ss < 16; ss++) {
            float kv[4], vv[4];
#pragma unroll
            for (int i = 0; i < 4; i++) { kv[i] = Ks[ss][e0 + i]; vv[i] = Vs[ss][d0 + i]; }
#pragma unroll
            for (int i = 0; i < 4; i++)
#pragma unroll
                for (int jj = 0; jj < 4; jj++) acc[i][jj] += kv[i] * vv[jj];
        }
        __syncthreads();
    }

    float* mo = Mp + ((size_t)blockIdx.y * 32 + bh) * (HD * HD);
#pragma unroll
    for (int i = 0; i < 4; i++)
#pragma unroll
        for (int jj = 0; jj < 4; jj++)
            mo[(e0 + i) * HD + d0 + jj] = acc[i][jj];
}

__global__ void reduce_m_kernel(const float* __restrict__ Mp, float* __restrict__ Mo)
{
    int i = blockIdx.x * 256 + threadIdx.x;
    float s = 0.0f;
#pragma unroll
    for (int p = 0; p < 16; p++) s += Mp[(size_t)p * 32 * HD * HD + i];
    Mo[i] = s;
}

/* OUT = Q @ M_h, fused fp16 output for the MLP GEMM */
__global__ void __launch_bounds__(256)
qm_kernel(const float* __restrict__ Q, const float* __restrict__ Mi,
          float* __restrict__ O, __half* __restrict__ Oh)
{
    __shared__ float Qs[64][68];
    __shared__ float Ms[64][68];

    const int bh = blockIdx.x;
    const int b  = bh >> 4, h = bh & 15;
    const int s0 = blockIdx.y * 64;
    const int tid = threadIdx.x;

#pragma unroll
    for (int p = 0; p < 4; p++) {
        int slot = tid + p * 256;
        int r = slot >> 4;
        int c = (slot & 15) * 4;
        *(float4*)&Qs[r][c] = *(const float4*)(Q + ((size_t)(b * SEQ + s0 + r)) * DIMC + h * HD + c);
        *(float4*)&Ms[r][c] = *(const float4*)(Mi + (size_t)bh * HD * HD + r * HD + c);
    }
    __syncthreads();

    const int r0 = (tid >> 4) * 4;
    const int c0 = (tid & 15) * 4;
    float acc[4][4] = {};
#pragma unroll
    for (int k = 0; k < 64; k++) {
        float qv[4], mv[4];
#pragma unroll
        for (int i = 0; i < 4; i++) qv[i] = Qs[r0 + i][k];
#pragma unroll
        for (int jj = 0; jj < 4; jj++) mv[jj] = Ms[k][c0 + jj];
#pragma unroll
        for (int i = 0; i < 4; i++)
#pragma unroll
            for (int jj = 0; jj < 4; jj++) acc[i][jj] += qv[i] * mv[jj];
    }
#pragma unroll
    for (int i = 0; i < 4; i++) {
        size_t base = ((size_t)(b * SEQ + s0 + r0 + i)) * DIMC + h * HD + c0;
#pragma unroll
        for (int jj = 0; jj < 4; jj++) O[base + jj] = acc[i][jj];
        *(__half2*)(Oh + base)     = __halves2half2(__float2half(acc[i][0]), __float2half(acc[i][1]));
        *(__half2*)(Oh + base + 2) = __halves2half2(__float2half(acc[i][2]), __float2half(acc[i][3]));
    }
}

/* ========================================================================= */
extern "C" void kernel_launch(void* const* d_in, const int* in_sizes, int n_in,
                              void* d_out, int out_size)
{
    const float* x  = (const float*)d_in[0];
    const float* Wq = (const float*)d_in[1];
    const float* bq = (const float*)d_in[2];
    const float* Wk = (const float*)d_in[3];
    const float* bk = (const float*)d_in[4];
    const float* Wv = (const float*)d_in[5];
    const float* bv = (const float*)d_in[6];
    const float* W1 = (const float*)d_in[7];
    const float* b1 = (const float*)d_in[8];
    const float* W2 = (const float*)d_in[9];
    const float* b2 = (const float*)d_in[10];
    float* Y = (float*)d_out;

    float *Q, *K, *V, *OUTP, *MP, *MM;
    cudaGetSymbolAddress((void**)&Q,    g_Q);
    cudaGetSymbolAddress((void**)&K,    g_K);
    cudaGetSymbolAddress((void**)&V,    g_V);
    cudaGetSymbolAddress((void**)&OUTP, g_OUT);
    cudaGetSymbolAddress((void**)&MP,   g_Mpart);
    cudaGetSymbolAddress((void**)&MM,   g_M);

    __half *xh, *xl, *oh, *hh, *wqkv, *w1h, *w2h;
    cudaGetSymbolAddress((void**)&xh,   g_xh);  cudaGetSymbolAddress((void**)&xl, g_xl);
    cudaGetSymbolAddress((void**)&oh,   g_oh);
    cudaGetSymbolAddress((void**)&hh,   g_hh);
    cudaGetSymbolAddress((void**)&wqkv, g_wqkv);
    cudaGetSymbolAddress((void**)&w1h,  g_w1h);
    cudaGetSymbolAddress((void**)&w2h,  g_w2h);

    cudaFuncSetAttribute(gemm_f16<1,3>, cudaFuncAttributeMaxDynamicSharedMemorySize, GSMEM_S1);
    cudaFuncSetAttribute(gemm_f16<0,1>, cudaFuncAttributeMaxDynamicSharedMemorySize, GSMEM_S0);
    cudaFuncSetAttribute(gemm_f16<0,2>, cudaFuncAttributeMaxDynamicSharedMemorySize, GSMEM_S0);

    const int NX = MTOT * DIMC;   /* 4.19M */
    const int NW = DIMC * DIMC;   /* 1.05M */
    dim3 sgx((NX / 4 + 255) / 256), sgw((NW / 4 + 255) / 256);

    /* x split (hi+lo); weights hi-only, QKV concatenated */
    split_kernel <<<sgx, 256>>>(x,  xh, xl, NX);
    tohalf_kernel<<<sgw, 256>>>(Wq, wqkv,          NW);
    tohalf_kernel<<<sgw, 256>>>(Wk, wqkv + NW,     NW);
    tohalf_kernel<<<sgw, 256>>>(Wv, wqkv + 2 * NW, NW);
    tohalf_kernel<<<sgw, 256>>>(W1, w1h, NW);
    tohalf_kernel<<<sgw, 256>>>(W2, w2h, NW);

    /* fused QKV projection: one GEMM over [4096 x 3072 x 1024] */
    dim3 qkvgrid(3 * DIMC / TN, MTOT / TM);   /* (24, 32) */
    gemm_f16<1,3><<<qkvgrid, NTHR, GSMEM_S1>>>(xh, xl, wqkv, bq, Q, nullptr,
                                               nullptr, nullptr, K, V, bk, bv);

    /* attention collapsed: out = Q @ (K^T V) per head, exact fp32 */
    kv_m_kernel<<<dim3(32, 16), 256>>>(K, V, MP);
    reduce_m_kernel<<<(32 * HD * HD) / 256, 256>>>(MP, MM);
    qm_kernel<<<dim3(32, SEQ / 64), 256>>>(Q, MM, OUTP, oh);

    /* MLP (plain fp16): h = gelu(OUT @ W1^T + b1); Y = x + OUT + h @ W2^T + b2 */
    dim3 ggrid(DIMC / TN, MTOT / TM);   /* (8, 32) */
    gemm_f16<0,1><<<ggrid, NTHR, GSMEM_S0>>>(oh, nullptr, w1h, b1, nullptr, hh,
                                             nullptr, nullptr, nullptr, nullptr, nullptr, nullptr);
    gemm_f16<0,2><<<ggrid, NTHR, GSMEM_S0>>>(hh, nullptr, w2h, b2, Y, nullptr,
                                             x, OUTP, nullptr, nullptr, nullptr, nullptr);
}

// round 15
// speedup vs baseline: 1.6661x; 1.0001x over previous
#include <cuda_runtime.h>
#include <cuda_fp16.h>
#include <math.h>
#include <stdint.h>

#define DIMC   1024
#define BATCH  2
#define SEQ    2048
#define MTOT   (BATCH*SEQ)      /* 4096 rows */
#define NHEAD  16
#define HD     64
#define QSCALE 0.125f           /* 64^-0.5 */

/* ------------------- scratch (allocations forbidden) ------------------- */
__device__ float g_Q  [MTOT * DIMC];
__device__ float g_K  [MTOT * DIMC];
__device__ float g_V  [MTOT * DIMC];
__device__ float g_OUT[MTOT * DIMC];
__device__ float g_Mpart[16 * BATCH * NHEAD * HD * HD];
__device__ float g_M  [BATCH * NHEAD * HD * HD];

/* fp16 operands */
__device__ __half g_xh  [MTOT * DIMC], g_xl[MTOT * DIMC];
__device__ __half g_oh  [MTOT * DIMC];
__device__ __half g_hh  [MTOT * DIMC];
__device__ __half g_wqkv[3 * DIMC * DIMC];    /* Wq | Wk | Wv  (fp16) */
__device__ __half g_w1h [DIMC * DIMC];
__device__ __half g_w2h [DIMC * DIMC];

/* ============================ asm helpers =============================== */
__device__ __forceinline__ uint32_t smem_u32(const void* p) {
    uint32_t a;
    asm("{ .reg .u64 t; cvta.to.shared.u64 t, %1; cvt.u32.u64 %0, t; }"
        : "=r"(a) : "l"(p));
    return a;
}
#define CP_ASYNC16(saddr, gptr) \
    asm volatile("cp.async.cg.shared.global [%0], [%1], 16;" \
                 :: "r"(saddr), "l"(gptr) : "memory")
#define CP_COMMIT()  asm volatile("cp.async.commit_group;" ::: "memory")
#define CP_WAIT(N)   asm volatile("cp.async.wait_group %0;" :: "n"(N) : "memory")

__device__ __forceinline__ void ldsm_x4(uint32_t& r0, uint32_t& r1,
                                        uint32_t& r2, uint32_t& r3, uint32_t addr) {
    asm volatile("ldmatrix.sync.aligned.m8n8.x4.shared.b16 {%0,%1,%2,%3}, [%4];"
                 : "=r"(r0), "=r"(r1), "=r"(r2), "=r"(r3) : "r"(addr));
}
__device__ __forceinline__ void mma_f16(float* c, const uint32_t* a,
                                        uint32_t b0, uint32_t b1) {
    asm volatile(
        "mma.sync.aligned.m16n8k16.row.col.f32.f16.f16.f32 "
        "{%0,%1,%2,%3},{%4,%5,%6,%7},{%8,%9},{%0,%1,%2,%3};"
        : "+f"(c[0]), "+f"(c[1]), "+f"(c[2]), "+f"(c[3])
        : "r"(a[0]), "r"(a[1]), "r"(a[2]), "r"(a[3]), "r"(b0), "r"(b1));
}

/* =========================================================================
 * fp16 GEMM (mma.sync.m16n8k16):
 *   C[m,n] = epi( sum_k A[m,k]*B[n,k] + bias[n] )
 * SPLIT=1: A ~ Ah+Al (fp16), acc += Ah*B + Al*B  (2 MMAs)
 * CTA tile 128x128, warptile 64x64 (4 warps, 128 threads), 2 CTAs/SM,
 * BK=32, 3-stage cp.async pipeline, one sync per chunk, 80B-padded smem rows.
 * EPI: 1 = gelu_exact -> fp16 Ch
 *      2 = fp32 C = acc + bias + r1 + r2
 *      3 = fused QKV: route by column range (Q gets *QSCALE), fp32 out
 * ========================================================================= */
#define TM 128
#define TN 128
#define BK 32
#define NCH (DIMC / BK)            /* 32 k-chunks */
#define PADB 80                    /* bytes per smem row (32 fp16 + pad) */
#define TILE_B (128 * PADB)        /* 10240 */
#define NSTAGE 3
#define NTHR 128

template<int SPLIT, int EPI>
__global__ void __launch_bounds__(NTHR, 2)
gemm_f16(const __half* __restrict__ Ah, const __half* __restrict__ Al,
         const __half* __restrict__ B,
         const float* __restrict__ bias, float* __restrict__ C,
         __half* __restrict__ Ch,
         const float* __restrict__ r1, const float* __restrict__ r2,
         float* __restrict__ CK, float* __restrict__ CV,
         const float* __restrict__ bk, const float* __restrict__ bv)
{
    constexpr int NT  = SPLIT ? 3 : 2;     /* tiles per stage            */
    constexpr int STB = NT * TILE_B;       /* bytes per stage            */
    constexpr int NCK = NT * 4;            /* 16B chunks per thread      */

    extern __shared__ char smem[];
    const uint32_t sbase = smem_u32(smem);

    const int tid  = threadIdx.x;
    const int wid  = tid >> 5;
    const int lane = tid & 31;
    const int wm   = wid >> 1;     /* 0..1 : 64-row slice */
    const int wn   = wid & 1;      /* 0..1 : 64-col slice */
    const int g    = lane >> 2;    /* 0..7 */
    const int t    = lane & 3;
    const int m0   = blockIdx.y * TM;
    const int n0   = blockIdx.x * TN;      /* EPI==3: column in 0..3071 */

    const char* srcs[NT];
    srcs[0] = (const char*)(Ah + (size_t)m0 * DIMC);
    if (SPLIT) {
        srcs[1] = (const char*)(Al + (size_t)m0 * DIMC);
        srcs[2] = (const char*)(B  + (size_t)n0 * DIMC);
    } else {
        srcs[1] = (const char*)(B  + (size_t)n0 * DIMC);
    }

    int cid[NCK], crow[NCK], ccol[NCK];
#pragma unroll
    for (int it = 0; it < NCK; it++) {
        int id = tid + it * NTHR;
        cid[it]  = id >> 9;                /* tile            */
        crow[it] = (id >> 2) & 127;        /* row 0..127      */
        ccol[it] = id & 3;                 /* 16B chunk 0..3  */
    }

    auto prefetch = [&](int ch, int buf) {
        const uint32_t sb = sbase + buf * STB;
#pragma unroll
        for (int it = 0; it < NCK; it++) {
            const char* gp = srcs[cid[it]] + (size_t)crow[it] * (DIMC * 2)
                           + ch * (BK * 2) + ccol[it] * 16;
            uint32_t sa = sb + cid[it] * TILE_B + crow[it] * PADB + ccol[it] * 16;
            CP_ASYNC16(sa, gp);
        }
        CP_COMMIT();
    };

    float acc[4][8][4];
#pragma unroll
    for (int i = 0; i < 4; i++)
#pragma unroll
        for (int j = 0; j < 8; j++)
#pragma unroll
            for (int q = 0; q < 4; q++) acc[i][j][q] = 0.0f;

    prefetch(0, 0);
    prefetch(1, 1);

    const uint32_t lm_off = (uint32_t)(lane & 15) * PADB + (uint32_t)(lane >> 4) * 16;

    int bufc = 0;
    for (int ch = 0; ch < NCH; ch++) {
        if (ch + 1 < NCH) { CP_WAIT(1); } else { CP_WAIT(0); }
        __syncthreads();

        if (ch + 2 < NCH) {
            int pf = bufc + 2; if (pf >= NSTAGE) pf -= NSTAGE;
            prefetch(ch + 2, pf);
        }

        const uint32_t sb  = sbase + bufc * STB;
        const uint32_t aht = sb;
        const uint32_t alt = sb + TILE_B;                 /* SPLIT only */
        const uint32_t bt  = sb + (NT - 1) * TILE_B;

#pragma unroll
        for (int ks = 0; ks < 2; ks++) {          /* two k16 steps per BK=32 */
            uint32_t bb[8][2];
#pragma unroll
            for (int j = 0; j < 8; j++) {
                uint32_t nrow = (uint32_t)(wn * 64 + j * 8 + g) * PADB + ks * 32 + t * 4;
                asm volatile("ld.shared.b32 %0, [%1];" : "=r"(bb[j][0]) : "r"(bt + nrow));
                asm volatile("ld.shared.b32 %0, [%1];" : "=r"(bb[j][1]) : "r"(bt + nrow + 16));
            }
#pragma unroll
            for (int i = 0; i < 4; i++) {
                uint32_t arow = (uint32_t)(wm * 64 + i * 16) * PADB + lm_off + ks * 32;
                uint32_t ah[4], al[4];
                ldsm_x4(ah[0], ah[1], ah[2], ah[3], aht + arow);
                if (SPLIT) ldsm_x4(al[0], al[1], al[2], al[3], alt + arow);
#pragma unroll
                for (int j = 0; j < 8; j++) {
                    mma_f16(acc[i][j], ah, bb[j][0], bb[j][1]);
                    if (SPLIT) mma_f16(acc[i][j], al, bb[j][0], bb[j][1]);
                }
            }
        }
        bufc = (bufc + 1 == NSTAGE) ? 0 : bufc + 1;
    }

    /* ---------------- epilogue: register-resident ---------------- */
    /* EPI==3: select output slice (Q/K/V) by global column range */
    const int which = (EPI == 3) ? (n0 >> 10) : 0;
    const float* bs = bias;
    float* Cw = C;
    float alpha = 1.0f;
    if (EPI == 3) {
        if (which == 1)      { bs = bk; Cw = CK; }
        else if (which == 2) { bs = bv; Cw = CV; }
        else                 { alpha = QSCALE; }
    }
    const int ncol0 = (EPI == 3) ? (n0 & 1023) : n0;

#pragma unroll
    for (int i = 0; i < 4; i++) {
        const int row0 = m0 + wm * 64 + i * 16 + g;
#pragma unroll
        for (int j = 0; j < 8; j++) {
            const int col = ncol0 + wn * 64 + j * 8 + 2 * t;
            float2 b2 = *(const float2*)(bs + col);
            float v[4] = { acc[i][j][0] + b2.x, acc[i][j][1] + b2.y,
                           acc[i][j][2] + b2.x, acc[i][j][3] + b2.y };
            size_t p0 = (size_t)row0 * DIMC + col;
            size_t p1 = (size_t)(row0 + 8) * DIMC + col;
            if (EPI == 3) {
#pragma unroll
                for (int q = 0; q < 4; q++) v[q] *= alpha;
                *(float2*)(Cw + p0) = make_float2(v[0], v[1]);
                *(float2*)(Cw + p1) = make_float2(v[2], v[3]);
            } else if (EPI == 1) {
#pragma unroll
                for (int q = 0; q < 4; q++)
                    v[q] = 0.5f * v[q] * (1.0f + erff(v[q] * 0.70710678118654752f));
                *(__half2*)(Ch + p0) = __halves2half2(__float2half(v[0]), __float2half(v[1]));
                *(__half2*)(Ch + p1) = __halves2half2(__float2half(v[2]), __float2half(v[3]));
            } else {   /* EPI == 2 */
                float2 x0 = *(const float2*)(r1 + p0), o0 = *(const float2*)(r2 + p0);
                float2 x1 = *(const float2*)(r1 + p1), o1 = *(const float2*)(r2 + p1);
                v[0] += x0.x + o0.x; v[1] += x0.y + o0.y;
                v[2] += x1.x + o1.x; v[3] += x1.y + o1.y;
                *(float2*)(Cw + p0) = make_float2(v[0], v[1]);
                *(float2*)(Cw + p1) = make_float2(v[2], v[3]);
            }
        }
    }
}

#define GSMEM_S1 (NSTAGE * 3 * TILE_B)   /* 92160 */
#define GSMEM_S0 (NSTAGE * 2 * TILE_B)   /* 61440 */

/* ================== fp32 -> fp16 (hi, lo) split ========================= */
__global__ void split_kernel(const float* __restrict__ in,
                             __half* __restrict__ hi,
                             __half* __restrict__ lo, int n)
{
    int i = (blockIdx.x * 256 + threadIdx.x) * 4;
    if (i >= n) return;
    float4 v = *(const float4*)(in + i);
    float f[4] = {v.x, v.y, v.z, v.w};
    __half h[4], l[4];
#pragma unroll
    for (int k = 0; k < 4; k++) {
        h[k] = __float2half(f[k]);
        l[k] = __float2half(f[k] - __half2float(h[k]));
    }
    *(__half2*)(hi + i)     = __halves2half2(h[0], h[1]);
    *(__half2*)(hi + i + 2) = __halves2half2(h[2], h[3]);
    *(__half2*)(lo + i)     = __halves2half2(l[0], l[1]);
    *(__half2*)(lo + i + 2) = __halves2half2(l[2], l[3]);
}

/* fp32 -> fp16 (hi only) for weights */
__global__ void tohalf_kernel(const float* __restrict__ in,
                              __half* __restrict__ hi, int n)
{
    int i = (blockIdx.x * 256 + threadIdx.x) * 4;
    if (i >= n) return;
    float4 v = *(const float4*)(in + i);
    *(__half2*)(hi + i)     = __halves2half2(__float2half(v.x), __float2half(v.y));
    *(__half2*)(hi + i + 2) = __halves2half2(__float2half(v.z), __float2half(v.w));
}

/* =========================================================================
 * Attention middle (exact fp32):  M_h = K_h^T V_h ;  OUT = Q_h @ M_h
 * ========================================================================= */
__global__ void __launch_bounds__(256)
kv_m_kernel(const float* __restrict__ K, const float* __restrict__ V,
            float* __restrict__ Mp)
{
    __shared__ float Ks[16][68];
    __shared__ float Vs[16][68];

    const int bh = blockIdx.x;               /* b*16 + h */
    const int b  = bh >> 4, h = bh & 15;
    const int s0 = blockIdx.y * 128;
    const int tid = threadIdx.x;
    const int e0 = (tid >> 4) * 4;
    const int d0 = (tid & 15) * 4;

    float acc[4][4] = {};
    const int lr = tid >> 4;
    const int lc = (tid & 15) * 4;

    for (int st = 0; st < 128; st += 16) {
        size_t gi = ((size_t)(b * SEQ + s0 + st + lr)) * DIMC + h * HD + lc;
        *(float4*)&Ks[lr][lc] = *(const float4*)(K + gi);
        *(float4*)&Vs[lr][lc] = *(const float4*)(V + gi);
        __syncthreads();
#pragma unroll
        for (int ss = 0; ss < 16; ss++) {
            float kv[4], vv[4];
#pragma unroll
            for (int i = 0; i < 4; i++) { kv[i] = Ks[ss][e0 + i]; vv[i] = Vs[ss][d0 + i]; }
#pragma unroll
            for (int i = 0; i < 4; i++)
#pragma unroll
                for (int jj = 0; jj < 4; jj++) acc[i][jj] += kv[i] * vv[jj];
        }
        __syncthreads();
    }

    float* mo = Mp + ((size_t)blockIdx.y * 32 + bh) * (HD * HD);
#pragma unroll
    for (int i = 0; i < 4; i++)
#pragma unroll
        for (int jj = 0; jj < 4; jj++)
            mo[(e0 + i) * HD + d0 + jj] = acc[i][jj];
}

__global__ void reduce_m_kernel(const float* __restrict__ Mp, float* __restrict__ Mo)
{
    int i = blockIdx.x * 256 + threadIdx.x;
    float s = 0.0f;
#pragma unroll
    for (int p = 0; p < 16; p++) s += Mp[(size_t)p * 32 * HD * HD + i];
    Mo[i] = s;
}

/* OUT = Q @ M_h, fused fp16 output for the MLP GEMM */
__global__ void __launch_bounds__(256)
qm_kernel(const float* __restrict__ Q, const float* __restrict__ Mi,
          float* __restrict__ O, __half* __restrict__ Oh)
{
    __shared__ float Qs[64][68];
    __shared__ float Ms[64][68];

    const int bh = blockIdx.x;
    const int b  = bh >> 4, h = bh & 15;
    const int s0 = blockIdx.y * 64;
    const int tid = threadIdx.x;

#pragma unroll
    for (int p = 0; p < 4; p++) {
        int slot = tid + p * 256;
        int r = slot >> 4;
        int c = (slot & 15) * 4;
        *(float4*)&Qs[r][c] = *(const float4*)(Q + ((size_t)(b * SEQ + s0 + r)) * DIMC + h * HD + c);
        *(float4*)&Ms[r][c] = *(const float4*)(Mi + (size_t)bh * HD * HD + r * HD + c);
    }
    __syncthreads();

    const int r0 = (tid >> 4) * 4;
    const int c0 = (tid & 15) * 4;
    float acc[4][4] = {};
#pragma unroll
    for (int k = 0; k < 64; k++) {
        float qv[4], mv[4];
#pragma unroll
        for (int i = 0; i < 4; i++) qv[i] = Qs[r0 + i][k];
#pragma unroll
        for (int jj = 0; jj < 4; jj++) mv[jj] = Ms[k][c0 + jj];
#pragma unroll
        for (int i = 0; i < 4; i++)
#pragma unroll
            for (int jj = 0; jj < 4; jj++) acc[i][jj] += qv[i] * mv[jj];
    }
#pragma unroll
    for (int i = 0; i < 4; i++) {
        size_t base = ((size_t)(b * SEQ + s0 + r0 + i)) * DIMC + h * HD + c0;
#pragma unroll
        for (int jj = 0; jj < 4; jj++) O[base + jj] = acc[i][jj];
        *(__half2*)(Oh + base)     = __halves2half2(__float2half(acc[i][0]), __float2half(acc[i][1]));
        *(__half2*)(Oh + base + 2) = __halves2half2(__float2half(acc[i][2]), __float2half(acc[i][3]));
    }
}

/* ========================================================================= */
extern "C" void kernel_launch(void* const* d_in, const int* in_sizes, int n_in,
                              void* d_out, int out_size)
{
    const float* x  = (const float*)d_in[0];
    const float* Wq = (const float*)d_in[1];
    const float* bq = (const float*)d_in[2];
    const float* Wk = (const float*)d_in[3];
    const float* bk = (const float*)d_in[4];
    const float* Wv = (const float*)d_in[5];
    const float* bv = (const float*)d_in[6];
    const float* W1 = (const float*)d_in[7];
    const float* b1 = (const float*)d_in[8];
    const float* W2 = (const float*)d_in[9];
    const float* b2 = (const float*)d_in[10];
    float* Y = (float*)d_out;

    float *Q, *K, *V, *OUTP, *MP, *MM;
    cudaGetSymbolAddress((void**)&Q,    g_Q);
    cudaGetSymbolAddress((void**)&K,    g_K);
    cudaGetSymbolAddress((void**)&V,    g_V);
    cudaGetSymbolAddress((void**)&OUTP, g_OUT);
    cudaGetSymbolAddress((void**)&MP,   g_Mpart);
    cudaGetSymbolAddress((void**)&MM,   g_M);

    __half *xh, *xl, *oh, *hh, *wqkv, *w1h, *w2h;
    cudaGetSymbolAddress((void**)&xh,   g_xh);  cudaGetSymbolAddress((void**)&xl, g_xl);
    cudaGetSymbolAddress((void**)&oh,   g_oh);
    cudaGetSymbolAddress((void**)&hh,   g_hh);
    cudaGetSymbolAddress((void**)&wqkv, g_wqkv);
    cudaGetSymbolAddress((void**)&w1h,  g_w1h);
    cudaGetSymbolAddress((void**)&w2h,  g_w2h);

    cudaFuncSetAttribute(gemm_f16<1,3>, cudaFuncAttributeMaxDynamicSharedMemorySize, GSMEM_S1);
    cudaFuncSetAttribute(gemm_f16<0,1>, cudaFuncAttributeMaxDynamicSharedMemorySize, GSMEM_S0);
    cudaFuncSetAttribute(gemm_f16<0,2>, cudaFuncAttributeMaxDynamicSharedMemorySize, GSMEM_S0);

    const int NX = MTOT * DIMC;   /* 4.19M */
    const int NW = DIMC * DIMC;   /* 1.05M */
    dim3 sgx((NX / 4 + 255) / 256), sgw((NW / 4 + 255) / 256);

    /* x split (hi+lo); weights hi-only, QKV concatenated */
    split_kernel <<<sgx, 256>>>(x,  xh, xl, NX);
    tohalf_kernel<<<sgw, 256>>>(Wq, wqkv,          NW);
    tohalf_kernel<<<sgw, 256>>>(Wk, wqkv + NW,     NW);
    tohalf_kernel<<<sgw, 256>>>(Wv, wqkv + 2 * NW, NW);
    tohalf_kernel<<<sgw, 256>>>(W1, w1h, NW);
    tohalf_kernel<<<sgw, 256>>>(W2, w2h, NW);

    /* fused QKV projection: one GEMM over [4096 x 3072 x 1024] */
    dim3 qkvgrid(3 * DIMC / TN, MTOT / TM);   /* (24, 32) */
    gemm_f16<1,3><<<qkvgrid, NTHR, GSMEM_S1>>>(xh, xl, wqkv, bq, Q, nullptr,
                                               nullptr, nullptr, K, V, bk, bv);

    /* attention collapsed: out = Q @ (K^T V) per head, exact fp32 */
    kv_m_kernel<<<dim3(32, 16), 256>>>(K, V, MP);
    reduce_m_kernel<<<(32 * HD * HD) / 256, 256>>>(MP, MM);
    qm_kernel<<<dim3(32, SEQ / 64), 256>>>(Q, MM, OUTP, oh);

    /* MLP (plain fp16): h = gelu(OUT @ W1^T + b1); Y = x + OUT + h @ W2^T + b2 */
    dim3 ggrid(DIMC / TN, MTOT / TM);   /* (8, 32) */
    gemm_f16<0,1><<<ggrid, NTHR, GSMEM_S0>>>(oh, nullptr, w1h, b1, nullptr, hh,
                                             nullptr, nullptr, nullptr, nullptr, nullptr, nullptr);
    gemm_f16<0,2><<<ggrid, NTHR, GSMEM_S0>>>(hh, nullptr, w2h, b2, Y, nullptr,
                                             x, OUTP, nullptr, nullptr, nullptr, nullptr);
}

// round 16
// speedup vs baseline: 1.8159x; 1.0899x over previous
#include <cuda_runtime.h>
#include <cuda_fp16.h>
#include <math.h>
#include <stdint.h>

#define DIMC   1024
#define BATCH  2
#define SEQ    2048
#define MTOT   (BATCH*SEQ)      /* 4096 rows */
#define NHEAD  16
#define HD     64
#define QSCALE 0.125f           /* 64^-0.5 */

/* ------------------- scratch (allocations forbidden) ------------------- */
__device__ float g_Q  [MTOT * DIMC];
__device__ float g_K  [MTOT * DIMC];
__device__ float g_V  [MTOT * DIMC];
__device__ float g_OUT[MTOT * DIMC];
__device__ float g_Mpart[16 * BATCH * NHEAD * HD * HD];
__device__ float g_M  [BATCH * NHEAD * HD * HD];

/* fp16 operands */
__device__ __half g_xh  [MTOT * DIMC], g_xl[MTOT * DIMC];
__device__ __half g_oh  [MTOT * DIMC];
__device__ __half g_hh  [MTOT * DIMC];
__device__ __half g_wqkv[3 * DIMC * DIMC];    /* Wq | Wk | Wv  (fp16) */
__device__ __half g_w1h [DIMC * DIMC];
__device__ __half g_w2h [DIMC * DIMC];

/* ============================ asm helpers =============================== */
__device__ __forceinline__ uint32_t smem_u32(const void* p) {
    uint32_t a;
    asm("{ .reg .u64 t; cvta.to.shared.u64 t, %1; cvt.u32.u64 %0, t; }"
        : "=r"(a) : "l"(p));
    return a;
}
#define CP_ASYNC16(saddr, gptr) \
    asm volatile("cp.async.cg.shared.global [%0], [%1], 16;" \
                 :: "r"(saddr), "l"(gptr) : "memory")
#define CP_COMMIT()  asm volatile("cp.async.commit_group;" ::: "memory")
#define CP_WAIT(N)   asm volatile("cp.async.wait_group %0;" :: "n"(N) : "memory")

__device__ __forceinline__ void ldsm_x4(uint32_t& r0, uint32_t& r1,
                                        uint32_t& r2, uint32_t& r3, uint32_t addr) {
    asm volatile("ldmatrix.sync.aligned.m8n8.x4.shared.b16 {%0,%1,%2,%3}, [%4];"
                 : "=r"(r0), "=r"(r1), "=r"(r2), "=r"(r3) : "r"(addr));
}
__device__ __forceinline__ void mma_f16(float* c, const uint32_t* a,
                                        uint32_t b0, uint32_t b1) {
    asm volatile(
        "mma.sync.aligned.m16n8k16.row.col.f32.f16.f16.f32 "
        "{%0,%1,%2,%3},{%4,%5,%6,%7},{%8,%9},{%0,%1,%2,%3};"
        : "+f"(c[0]), "+f"(c[1]), "+f"(c[2]), "+f"(c[3])
        : "r"(a[0]), "r"(a[1]), "r"(a[2]), "r"(a[3]), "r"(b0), "r"(b1));
}

/* =========================================================================
 * fp16 GEMM (mma.sync.m16n8k16):
 *   C[m,n] = epi( sum_k A[m,k]*B[n,k] + bias[n] )
 * SPLIT=1 layout carries an Al tile; per-CTA runtime flag decides whether the
 * correction MMA is actually issued (EPI==3: only Q columns use it).
 * CTA tile 128x128, warptile 64x64 (4 warps, 128 threads), 2 CTAs/SM,
 * BK=32, 3-stage cp.async pipeline, one sync per chunk, 80B-padded smem rows.
 * EPI: 1 = gelu_exact -> fp16 Ch
 *      2 = fp32 C = acc + bias + r1 + r2
 *      3 = fused QKV: route by column range (Q: *QSCALE + split-A; K,V plain)
 * ========================================================================= */
#define TM 128
#define TN 128
#define BK 32
#define NCH (DIMC / BK)            /* 32 k-chunks */
#define PADB 80                    /* bytes per smem row (32 fp16 + pad) */
#define TILE_B (128 * PADB)        /* 10240 */
#define NSTAGE 3
#define NTHR 128

template<int SPLIT, int EPI>
__global__ void __launch_bounds__(NTHR, 2)
gemm_f16(const __half* __restrict__ Ah, const __half* __restrict__ Al,
         const __half* __restrict__ B,
         const float* __restrict__ bias, float* __restrict__ C,
         __half* __restrict__ Ch,
         const float* __restrict__ r1, const float* __restrict__ r2,
         float* __restrict__ CK, float* __restrict__ CV,
         const float* __restrict__ bk, const float* __restrict__ bv)
{
    constexpr int NT  = SPLIT ? 3 : 2;     /* tiles per stage            */
    constexpr int STB = NT * TILE_B;       /* bytes per stage            */
    constexpr int NCK = NT * 4;            /* 16B chunks per thread      */

    extern __shared__ char smem[];
    const uint32_t sbase = smem_u32(smem);

    const int tid  = threadIdx.x;
    const int wid  = tid >> 5;
    const int lane = tid & 31;
    const int wm   = wid >> 1;     /* 0..1 : 64-row slice */
    const int wn   = wid & 1;      /* 0..1 : 64-col slice */
    const int g    = lane >> 2;    /* 0..7 */
    const int t    = lane & 3;
    const int m0   = blockIdx.y * TM;
    const int n0   = blockIdx.x * TN;      /* EPI==3: column in 0..3071 */

    /* Q columns get the xl-correction MMA; K,V run plain fp16 */
    const bool do_split = SPLIT && ((EPI != 3) || (n0 < DIMC));

    const char* srcs[NT];
    srcs[0] = (const char*)(Ah + (size_t)m0 * DIMC);
    if (SPLIT) {
        srcs[1] = (const char*)(Al + (size_t)m0 * DIMC);
        srcs[2] = (const char*)(B  + (size_t)n0 * DIMC);
    } else {
        srcs[1] = (const char*)(B  + (size_t)n0 * DIMC);
    }

    int cid[NCK], crow[NCK], ccol[NCK];
#pragma unroll
    for (int it = 0; it < NCK; it++) {
        int id = tid + it * NTHR;
        cid[it]  = id >> 9;                /* tile            */
        crow[it] = (id >> 2) & 127;        /* row 0..127      */
        ccol[it] = id & 3;                 /* 16B chunk 0..3  */
    }

    auto prefetch = [&](int ch, int buf) {
        const uint32_t sb = sbase + buf * STB;
#pragma unroll
        for (int it = 0; it < NCK; it++) {
            if (SPLIT && cid[it] == 1 && !do_split) continue;  /* skip Al tile */
            const char* gp = srcs[cid[it]] + (size_t)crow[it] * (DIMC * 2)
                           + ch * (BK * 2) + ccol[it] * 16;
            uint32_t sa = sb + cid[it] * TILE_B + crow[it] * PADB + ccol[it] * 16;
            CP_ASYNC16(sa, gp);
        }
        CP_COMMIT();
    };

    float acc[4][8][4];
#pragma unroll
    for (int i = 0; i < 4; i++)
#pragma unroll
        for (int j = 0; j < 8; j++)
#pragma unroll
            for (int q = 0; q < 4; q++) acc[i][j][q] = 0.0f;

    prefetch(0, 0);
    prefetch(1, 1);

    const uint32_t lm_off = (uint32_t)(lane & 15) * PADB + (uint32_t)(lane >> 4) * 16;

    int bufc = 0;
    for (int ch = 0; ch < NCH; ch++) {
        if (ch + 1 < NCH) { CP_WAIT(1); } else { CP_WAIT(0); }
        __syncthreads();

        if (ch + 2 < NCH) {
            int pf = bufc + 2; if (pf >= NSTAGE) pf -= NSTAGE;
            prefetch(ch + 2, pf);
        }

        const uint32_t sb  = sbase + bufc * STB;
        const uint32_t aht = sb;
        const uint32_t alt = sb + TILE_B;                 /* SPLIT only */
        const uint32_t bt  = sb + (NT - 1) * TILE_B;

#pragma unroll
        for (int ks = 0; ks < 2; ks++) {          /* two k16 steps per BK=32 */
            uint32_t bb[8][2];
#pragma unroll
            for (int j = 0; j < 8; j++) {
                uint32_t nrow = (uint32_t)(wn * 64 + j * 8 + g) * PADB + ks * 32 + t * 4;
                asm volatile("ld.shared.b32 %0, [%1];" : "=r"(bb[j][0]) : "r"(bt + nrow));
                asm volatile("ld.shared.b32 %0, [%1];" : "=r"(bb[j][1]) : "r"(bt + nrow + 16));
            }
#pragma unroll
            for (int i = 0; i < 4; i++) {
                uint32_t arow = (uint32_t)(wm * 64 + i * 16) * PADB + lm_off + ks * 32;
                uint32_t ah[4], al[4];
                ldsm_x4(ah[0], ah[1], ah[2], ah[3], aht + arow);
                if (SPLIT && do_split) ldsm_x4(al[0], al[1], al[2], al[3], alt + arow);
#pragma unroll
                for (int j = 0; j < 8; j++) {
                    mma_f16(acc[i][j], ah, bb[j][0], bb[j][1]);
                    if (SPLIT && do_split) mma_f16(acc[i][j], al, bb[j][0], bb[j][1]);
                }
            }
        }
        bufc = (bufc + 1 == NSTAGE) ? 0 : bufc + 1;
    }

    /* ---------------- epilogue: register-resident ---------------- */
    const int which = (EPI == 3) ? (n0 >> 10) : 0;
    const float* bs = bias;
    float* Cw = C;
    float alpha = 1.0f;
    if (EPI == 3) {
        if (which == 1)      { bs = bk; Cw = CK; }
        else if (which == 2) { bs = bv; Cw = CV; }
        else                 { alpha = QSCALE; }
    }
    const int ncol0 = (EPI == 3) ? (n0 & 1023) : n0;

#pragma unroll
    for (int i = 0; i < 4; i++) {
        const int row0 = m0 + wm * 64 + i * 16 + g;
#pragma unroll
        for (int j = 0; j < 8; j++) {
            const int col = ncol0 + wn * 64 + j * 8 + 2 * t;
            float2 b2 = *(const float2*)(bs + col);
            float v[4] = { acc[i][j][0] + b2.x, acc[i][j][1] + b2.y,
                           acc[i][j][2] + b2.x, acc[i][j][3] + b2.y };
            size_t p0 = (size_t)row0 * DIMC + col;
            size_t p1 = (size_t)(row0 + 8) * DIMC + col;
            if (EPI == 3) {
#pragma unroll
                for (int q = 0; q < 4; q++) v[q] *= alpha;
                *(float2*)(Cw + p0) = make_float2(v[0], v[1]);
                *(float2*)(Cw + p1) = make_float2(v[2], v[3]);
            } else if (EPI == 1) {
#pragma unroll
                for (int q = 0; q < 4; q++)
                    v[q] = 0.5f * v[q] * (1.0f + erff(v[q] * 0.70710678118654752f));
                *(__half2*)(Ch + p0) = __halves2half2(__float2half(v[0]), __float2half(v[1]));
                *(__half2*)(Ch + p1) = __halves2half2(__float2half(v[2]), __float2half(v[3]));
            } else {   /* EPI == 2 */
                float2 x0 = *(const float2*)(r1 + p0), o0 = *(const float2*)(r2 + p0);
                float2 x1 = *(const float2*)(r1 + p1), o1 = *(const float2*)(r2 + p1);
                v[0] += x0.x + o0.x; v[1] += x0.y + o0.y;
                v[2] += x1.x + o1.x; v[3] += x1.y + o1.y;
                *(float2*)(Cw + p0) = make_float2(v[0], v[1]);
                *(float2*)(Cw + p1) = make_float2(v[2], v[3]);
            }
        }
    }
}

#define GSMEM_S1 (NSTAGE * 3 * TILE_B)   /* 92160 */
#define GSMEM_S0 (NSTAGE * 2 * TILE_B)   /* 61440 */

/* ========== ONE conversion kernel for all inputs (branch by range) ====== */
#define X4  ((MTOT * DIMC) / 4)      /* 1048576 float4 */
#define W4  ((DIMC * DIMC) / 4)      /*  262144 float4 */
#define CONV_BLOCKS ((X4 + 5 * W4) / 256)   /* 9216 */

__global__ void convert_all(const float* __restrict__ x,
                            const float* __restrict__ Wq, const float* __restrict__ Wk,
                            const float* __restrict__ Wv, const float* __restrict__ W1,
                            const float* __restrict__ W2,
                            __half* __restrict__ xh, __half* __restrict__ xl,
                            __half* __restrict__ wqkv,
                            __half* __restrict__ w1h, __half* __restrict__ w2h)
{
    int id = blockIdx.x * 256 + threadIdx.x;   /* float4 index */
    const float* src; __half* dh; __half* dl = nullptr; int off;
    if (id < X4)               { src = x;  dh = xh;            dl = xl; off = id; }
    else if (id < X4 + W4)     { src = Wq; dh = wqkv;                   off = id - X4; }
    else if (id < X4 + 2 * W4) { src = Wk; dh = wqkv + 4 * W4;          off = id - X4 - W4; }
    else if (id < X4 + 3 * W4) { src = Wv; dh = wqkv + 8 * W4;          off = id - X4 - 2 * W4; }
    else if (id < X4 + 4 * W4) { src = W1; dh = w1h;                    off = id - X4 - 3 * W4; }
    else                       { src = W2; dh = w2h;                    off = id - X4 - 4 * W4; }

    int i = off * 4;
    float4 v = *(const float4*)(src + i);
    float f[4] = {v.x, v.y, v.z, v.w};
    __half h[4];
#pragma unroll
    for (int k = 0; k < 4; k++) h[k] = __float2half(f[k]);
    *(__half2*)(dh + i)     = __halves2half2(h[0], h[1]);
    *(__half2*)(dh + i + 2) = __halves2half2(h[2], h[3]);
    if (dl) {
        __half l[4];
#pragma unroll
        for (int k = 0; k < 4; k++) l[k] = __float2half(f[k] - __half2float(h[k]));
        *(__half2*)(dl + i)     = __halves2half2(l[0], l[1]);
        *(__half2*)(dl + i + 2) = __halves2half2(l[2], l[3]);
    }
}

/* =========================================================================
 * Attention middle (exact fp32):  M_h = K_h^T V_h ;  OUT = Q_h @ M_h
 * ========================================================================= */
__global__ void __launch_bounds__(256)
kv_m_kernel(const float* __restrict__ K, const float* __restrict__ V,
            float* __restrict__ Mp)
{
    __shared__ float Ks[32][68];
    __shared__ float Vs[32][68];

    const int bh = blockIdx.x;               /* b*16 + h */
    const int b  = bh >> 4, h = bh & 15;
    const int s0 = blockIdx.y * 128;
    const int tid = threadIdx.x;
    const int e0 = (tid >> 4) * 4;
    const int d0 = (tid & 15) * 4;

    float acc[4][4] = {};

    for (int st = 0; st < 128; st += 32) {
#pragma unroll
        for (int p = 0; p < 2; p++) {
            int slot = tid + p * 256;            /* 0..511 */
            int lr = slot >> 4;                  /* 0..31  */
            int lc = (slot & 15) * 4;            /* 0..60  */
            size_t gi = ((size_t)(b * SEQ + s0 + st + lr)) * DIMC + h * HD + lc;
            *(float4*)&Ks[lr][lc] = *(const float4*)(K + gi);
            *(float4*)&Vs[lr][lc] = *(const float4*)(V + gi);
        }
        __syncthreads();
#pragma unroll
        for (int ss = 0; ss < 32; ss++) {
            float4 kv = *(const float4*)&Ks[ss][e0];
            float4 vv = *(const float4*)&Vs[ss][d0];
            float ka[4] = {kv.x, kv.y, kv.z, kv.w};
            float va[4] = {vv.x, vv.y, vv.z, vv.w};
#pragma unroll
            for (int i = 0; i < 4; i++)
#pragma unroll
                for (int jj = 0; jj < 4; jj++) acc[i][jj] += ka[i] * va[jj];
        }
        __syncthreads();
    }

    float* mo = Mp + ((size_t)blockIdx.y * 32 + bh) * (HD * HD);
#pragma unroll
    for (int i = 0; i < 4; i++)
#pragma unroll
        for (int jj = 0; jj < 4; jj++)
            mo[(e0 + i) * HD + d0 + jj] = acc[i][jj];
}

__global__ void reduce_m_kernel(const float* __restrict__ Mp, float* __restrict__ Mo)
{
    int i = blockIdx.x * 256 + threadIdx.x;
    float s = 0.0f;
#pragma unroll
    for (int p = 0; p < 16; p++) s += Mp[(size_t)p * 32 * HD * HD + i];
    Mo[i] = s;
}

/* OUT = Q @ M_h, fused fp16 output for the MLP GEMM */
__global__ void __launch_bounds__(256)
qm_kernel(const float* __restrict__ Q, const float* __restrict__ Mi,
          float* __restrict__ O, __half* __restrict__ Oh)
{
    __shared__ float Qs[64][68];
    __shared__ float Ms[64][68];

    const int bh = blockIdx.x;
    const int b  = bh >> 4, h = bh & 15;
    const int s0 = blockIdx.y * 64;
    const int tid = threadIdx.x;

#pragma unroll
    for (int p = 0; p < 4; p++) {
        int slot = tid + p * 256;
        int r = slot >> 4;
        int c = (slot & 15) * 4;
        *(float4*)&Qs[r][c] = *(const float4*)(Q + ((size_t)(b * SEQ + s0 + r)) * DIMC + h * HD + c);
        *(float4*)&Ms[r][c] = *(const float4*)(Mi + (size_t)bh * HD * HD + r * HD + c);
    }
    __syncthreads();

    const int r0 = (tid >> 4) * 4;
    const int c0 = (tid & 15) * 4;
    float acc[4][4] = {};
#pragma unroll
    for (int k = 0; k < 64; k++) {
        float qv[4], mv[4];
#pragma unroll
        for (int i = 0; i < 4; i++) qv[i] = Qs[r0 + i][k];
#pragma unroll
        for (int jj = 0; jj < 4; jj++) mv[jj] = Ms[k][c0 + jj];
#pragma unroll
        for (int i = 0; i < 4; i++)
#pragma unroll
            for (int jj = 0; jj < 4; jj++) acc[i][jj] += qv[i] * mv[jj];
    }
#pragma unroll
    for (int i = 0; i < 4; i++) {
        size_t base = ((size_t)(b * SEQ + s0 + r0 + i)) * DIMC + h * HD + c0;
#pragma unroll
        for (int jj = 0; jj < 4; jj++) O[base + jj] = acc[i][jj];
        *(__half2*)(Oh + base)     = __halves2half2(__float2half(acc[i][0]), __float2half(acc[i][1]));
        *(__half2*)(Oh + base + 2) = __halves2half2(__float2half(acc[i][2]), __float2half(acc[i][3]));
    }
}

/* ========================================================================= */
extern "C" void kernel_launch(void* const* d_in, const int* in_sizes, int n_in,
                              void* d_out, int out_size)
{
    const float* x  = (const float*)d_in[0];
    const float* Wq = (const float*)d_in[1];
    const float* bq = (const float*)d_in[2];
    const float* Wk = (const float*)d_in[3];
    const float* bk = (const float*)d_in[4];
    const float* Wv = (const float*)d_in[5];
    const float* bv = (const float*)d_in[6];
    const float* W1 = (const float*)d_in[7];
    const float* b1 = (const float*)d_in[8];
    const float* W2 = (const float*)d_in[9];
    const float* b2 = (const float*)d_in[10];
    float* Y = (float*)d_out;

    float *Q, *K, *V, *OUTP, *MP, *MM;
    cudaGetSymbolAddress((void**)&Q,    g_Q);
    cudaGetSymbolAddress((void**)&K,    g_K);
    cudaGetSymbolAddress((void**)&V,    g_V);
    cudaGetSymbolAddress((void**)&OUTP, g_OUT);
    cudaGetSymbolAddress((void**)&MP,   g_Mpart);
    cudaGetSymbolAddress((void**)&MM,   g_M);

    __half *xh, *xl, *oh, *hh, *wqkv, *w1h, *w2h;
    cudaGetSymbolAddress((void**)&xh,   g_xh);  cudaGetSymbolAddress((void**)&xl, g_xl);
    cudaGetSymbolAddress((void**)&oh,   g_oh);
    cudaGetSymbolAddress((void**)&hh,   g_hh);
    cudaGetSymbolAddress((void**)&wqkv, g_wqkv);
    cudaGetSymbolAddress((void**)&w1h,  g_w1h);
    cudaGetSymbolAddress((void**)&w2h,  g_w2h);

    cudaFuncSetAttribute(gemm_f16<1,3>, cudaFuncAttributeMaxDynamicSharedMemorySize, GSMEM_S1);
    cudaFuncSetAttribute(gemm_f16<0,1>, cudaFuncAttributeMaxDynamicSharedMemorySize, GSMEM_S0);
    cudaFuncSetAttribute(gemm_f16<0,2>, cudaFuncAttributeMaxDynamicSharedMemorySize, GSMEM_S0);

    /* one conversion kernel for x (split) + all 5 weights (hi-only) */
    convert_all<<<CONV_BLOCKS, 256>>>(x, Wq, Wk, Wv, W1, W2,
                                      xh, xl, wqkv, w1h, w2h);

    /* fused QKV projection: one GEMM over [4096 x 3072 x 1024]
       Q columns: split-A (2 MMAs); K,V columns: plain (1 MMA) */
    dim3 qkvgrid(3 * DIMC / TN, MTOT / TM);   /* (24, 32) */
    gemm_f16<1,3><<<qkvgrid, NTHR, GSMEM_S1>>>(xh, xl, wqkv, bq, Q, nullptr,
                                               nullptr, nullptr, K, V, bk, bv);

    /* attention collapsed: out = Q @ (K^T V) per head, exact fp32 */
    kv_m_kernel<<<dim3(32, 16), 256>>>(K, V, MP);
    reduce_m_kernel<<<(32 * HD * HD) / 256, 256>>>(MP, MM);
    qm_kernel<<<dim3(32, SEQ / 64), 256>>>(Q, MM, OUTP, oh);

    /* MLP (plain fp16): h = gelu(OUT @ W1^T + b1); Y = x + OUT + h @ W2^T + b2 */
    dim3 ggrid(DIMC / TN, MTOT / TM);   /* (8, 32) */
    gemm_f16<0,1><<<ggrid, NTHR, GSMEM_S0>>>(oh, nullptr, w1h, b1, nullptr, hh,
                                             nullptr, nullptr, nullptr, nullptr, nullptr, nullptr);
    gemm_f16<0,2><<<ggrid, NTHR, GSMEM_S0>>>(hh, nullptr, w2h, b2, Y, nullptr,
                                             x, OUTP, nullptr, nullptr, nullptr, nullptr);
}

// round 17
// speedup vs baseline: 2.3905x; 1.3164x over previous
#include <cuda_runtime.h>
#include <cuda_fp16.h>
#include <math.h>
#include <stdint.h>

#define DIMC   1024
#define BATCH  2
#define SEQ    2048
#define MTOT   (BATCH*SEQ)      /* 4096 rows */
#define NHEAD  16
#define HD     64
#define QSCALE 0.125f           /* 64^-0.5 */

/* ------------------- scratch (allocations forbidden) ------------------- */
__device__ float g_Q  [MTOT * DIMC];
__device__ float g_K  [MTOT * DIMC];
__device__ float g_V  [MTOT * DIMC];
__device__ float g_OUT[MTOT * DIMC];
__device__ float g_Mpart[16 * BATCH * NHEAD * HD * HD];
__device__ float g_M  [BATCH * NHEAD * HD * HD];

/* fp16 operands */
__device__ __half g_xh  [MTOT * DIMC];
__device__ __half g_oh  [MTOT * DIMC];
__device__ __half g_hh  [MTOT * DIMC];
__device__ __half g_wqkv[3 * DIMC * DIMC];    /* Wq | Wk | Wv  (fp16) */
__device__ __half g_w1h [DIMC * DIMC];
__device__ __half g_w2h [DIMC * DIMC];

/* ============================ asm helpers =============================== */
__device__ __forceinline__ uint32_t smem_u32(const void* p) {
    uint32_t a;
    asm("{ .reg .u64 t; cvta.to.shared.u64 t, %1; cvt.u32.u64 %0, t; }"
        : "=r"(a) : "l"(p));
    return a;
}
#define CP_ASYNC16(saddr, gptr) \
    asm volatile("cp.async.cg.shared.global [%0], [%1], 16;" \
                 :: "r"(saddr), "l"(gptr) : "memory")
#define CP_COMMIT()  asm volatile("cp.async.commit_group;" ::: "memory")
#define CP_WAIT(N)   asm volatile("cp.async.wait_group %0;" :: "n"(N) : "memory")

__device__ __forceinline__ void ldsm_x4(uint32_t& r0, uint32_t& r1,
                                        uint32_t& r2, uint32_t& r3, uint32_t addr) {
    asm volatile("ldmatrix.sync.aligned.m8n8.x4.shared.b16 {%0,%1,%2,%3}, [%4];"
                 : "=r"(r0), "=r"(r1), "=r"(r2), "=r"(r3) : "r"(addr));
}
__device__ __forceinline__ void mma_f16(float* c, const uint32_t* a,
                                        uint32_t b0, uint32_t b1) {
    asm volatile(
        "mma.sync.aligned.m16n8k16.row.col.f32.f16.f16.f32 "
        "{%0,%1,%2,%3},{%4,%5,%6,%7},{%8,%9},{%0,%1,%2,%3};"
        : "+f"(c[0]), "+f"(c[1]), "+f"(c[2]), "+f"(c[3])
        : "r"(a[0]), "r"(a[1]), "r"(a[2]), "r"(a[3]), "r"(b0), "r"(b1));
}

/* =========================================================================
 * Plain fp16 GEMM (mma.sync.m16n8k16, fp32 accumulate):
 *   C[m,n] = epi( sum_k A[m,k]*B[n,k] + bias[n] )
 * CTA tile 128x128, warptile 64x64 (4 warps, 128 threads), 2 CTAs/SM,
 * BK=32, 4-stage cp.async pipeline, one sync per chunk, 80B-padded smem rows.
 * EPI: 1 = gelu_exact -> fp16 Ch
 *      2 = fp32 C = acc + bias + r1 + r2
 *      3 = fused QKV: route by column range (Q gets *QSCALE)
 * ========================================================================= */
#define TM 128
#define TN 128
#define BK 32
#define NCH (DIMC / BK)            /* 32 k-chunks */
#define PADB 80                    /* bytes per smem row (32 fp16 + pad) */
#define TILE_B (128 * PADB)        /* 10240 */
#define NSTAGE 4
#define STB (2 * TILE_B)           /* A + B tiles per stage */
#define GSMEM (NSTAGE * STB)       /* 81920 */
#define NTHR 128

template<int EPI>
__global__ void __launch_bounds__(NTHR, 2)
gemm_f16(const __half* __restrict__ A, const __half* __restrict__ B,
         const float* __restrict__ bias, float* __restrict__ C,
         __half* __restrict__ Ch,
         const float* __restrict__ r1, const float* __restrict__ r2,
         float* __restrict__ CK, float* __restrict__ CV,
         const float* __restrict__ bk, const float* __restrict__ bv)
{
    extern __shared__ char smem[];
    const uint32_t sbase = smem_u32(smem);

    const int tid  = threadIdx.x;
    const int wid  = tid >> 5;
    const int lane = tid & 31;
    const int wm   = wid >> 1;     /* 0..1 : 64-row slice */
    const int wn   = wid & 1;      /* 0..1 : 64-col slice */
    const int g    = lane >> 2;    /* 0..7 */
    const int t    = lane & 3;
    const int m0   = blockIdx.y * TM;
    const int n0   = blockIdx.x * TN;      /* EPI==3: column in 0..3071 */

    const char* srcA = (const char*)(A + (size_t)m0 * DIMC);
    const char* srcB = (const char*)(B + (size_t)n0 * DIMC);

    /* per-thread cp.async mapping: 8 x 16B chunks per stage (2 tiles) */
    int cid[8], crow[8], ccol[8];
#pragma unroll
    for (int it = 0; it < 8; it++) {
        int id = tid + it * NTHR;          /* 0..1023 */
        cid[it]  = id >> 9;                /* tile 0..1      */
        crow[it] = (id >> 2) & 127;        /* row 0..127     */
        ccol[it] = id & 3;                 /* 16B chunk 0..3 */
    }

    auto prefetch = [&](int ch, int buf) {
        const uint32_t sb = sbase + buf * STB;
#pragma unroll
        for (int it = 0; it < 8; it++) {
            const char* gp = (cid[it] ? srcB : srcA)
                           + (size_t)crow[it] * (DIMC * 2)
                           + ch * (BK * 2) + ccol[it] * 16;
            uint32_t sa = sb + cid[it] * TILE_B + crow[it] * PADB + ccol[it] * 16;
            CP_ASYNC16(sa, gp);
        }
        CP_COMMIT();
    };

    float acc[4][8][4];
#pragma unroll
    for (int i = 0; i < 4; i++)
#pragma unroll
        for (int j = 0; j < 8; j++)
#pragma unroll
            for (int q = 0; q < 4; q++) acc[i][j][q] = 0.0f;

    prefetch(0, 0);
    prefetch(1, 1);
    prefetch(2, 2);

    const uint32_t lm_off = (uint32_t)(lane & 15) * PADB + (uint32_t)(lane >> 4) * 16;

    int bufc = 0;
    for (int ch = 0; ch < NCH; ch++) {
        if (ch + 2 < NCH) { CP_WAIT(2); } else { CP_WAIT(0); }
        __syncthreads();

        if (ch + 3 < NCH) {
            int pf = bufc + 3; if (pf >= NSTAGE) pf -= NSTAGE;
            prefetch(ch + 3, pf);
        }

        const uint32_t at = sbase + bufc * STB;
        const uint32_t bt = at + TILE_B;

#pragma unroll
        for (int ks = 0; ks < 2; ks++) {          /* two k16 steps per BK=32 */
            uint32_t bb[8][2];
#pragma unroll
            for (int j = 0; j < 8; j++) {
                uint32_t nrow = (uint32_t)(wn * 64 + j * 8 + g) * PADB + ks * 32 + t * 4;
                asm volatile("ld.shared.b32 %0, [%1];" : "=r"(bb[j][0]) : "r"(bt + nrow));
                asm volatile("ld.shared.b32 %0, [%1];" : "=r"(bb[j][1]) : "r"(bt + nrow + 16));
            }
#pragma unroll
            for (int i = 0; i < 4; i++) {
                uint32_t arow = (uint32_t)(wm * 64 + i * 16) * PADB + lm_off + ks * 32;
                uint32_t ar[4];
                ldsm_x4(ar[0], ar[1], ar[2], ar[3], at + arow);
#pragma unroll
                for (int j = 0; j < 8; j++)
                    mma_f16(acc[i][j], ar, bb[j][0], bb[j][1]);
            }
        }
        bufc = (bufc + 1 == NSTAGE) ? 0 : bufc + 1;
    }

    /* ---------------- epilogue: register-resident ---------------- */
    const int which = (EPI == 3) ? (n0 >> 10) : 0;
    const float* bs = bias;
    float* Cw = C;
    float alpha = 1.0f;
    if (EPI == 3) {
        if (which == 1)      { bs = bk; Cw = CK; }
        else if (which == 2) { bs = bv; Cw = CV; }
        else                 { alpha = QSCALE; }
    }
    const int ncol0 = (EPI == 3) ? (n0 & 1023) : n0;

#pragma unroll
    for (int i = 0; i < 4; i++) {
        const int row0 = m0 + wm * 64 + i * 16 + g;
#pragma unroll
        for (int j = 0; j < 8; j++) {
            const int col = ncol0 + wn * 64 + j * 8 + 2 * t;
            float2 b2 = *(const float2*)(bs + col);
            float v[4] = { acc[i][j][0] + b2.x, acc[i][j][1] + b2.y,
                           acc[i][j][2] + b2.x, acc[i][j][3] + b2.y };
            size_t p0 = (size_t)row0 * DIMC + col;
            size_t p1 = (size_t)(row0 + 8) * DIMC + col;
            if (EPI == 3) {
#pragma unroll
                for (int q = 0; q < 4; q++) v[q] *= alpha;
                *(float2*)(Cw + p0) = make_float2(v[0], v[1]);
                *(float2*)(Cw + p1) = make_float2(v[2], v[3]);
            } else if (EPI == 1) {
#pragma unroll
                for (int q = 0; q < 4; q++)
                    v[q] = 0.5f * v[q] * (1.0f + erff(v[q] * 0.70710678118654752f));
                *(__half2*)(Ch + p0) = __halves2half2(__float2half(v[0]), __float2half(v[1]));
                *(__half2*)(Ch + p1) = __halves2half2(__float2half(v[2]), __float2half(v[3]));
            } else {   /* EPI == 2 */
                float2 x0 = *(const float2*)(r1 + p0), o0 = *(const float2*)(r2 + p0);
                float2 x1 = *(const float2*)(r1 + p1), o1 = *(const float2*)(r2 + p1);
                v[0] += x0.x + o0.x; v[1] += x0.y + o0.y;
                v[2] += x1.x + o1.x; v[3] += x1.y + o1.y;
                *(float2*)(Cw + p0) = make_float2(v[0], v[1]);
                *(float2*)(Cw + p1) = make_float2(v[2], v[3]);
            }
        }
    }
}

/* ========== ONE conversion kernel for all inputs (branch by range) ====== */
#define X4  ((MTOT * DIMC) / 4)      /* 1048576 float4 */
#define W4  ((DIMC * DIMC) / 4)      /*  262144 float4 */
#define CONV_BLOCKS ((X4 + 5 * W4) / 256)   /* 9216 */

__global__ void convert_all(const float* __restrict__ x,
                            const float* __restrict__ Wq, const float* __restrict__ Wk,
                            const float* __restrict__ Wv, const float* __restrict__ W1,
                            const float* __restrict__ W2,
                            __half* __restrict__ xh, __half* __restrict__ wqkv,
                            __half* __restrict__ w1h, __half* __restrict__ w2h)
{
    int id = blockIdx.x * 256 + threadIdx.x;   /* float4 index */
    const float* src; __half* dh; int off;
    if (id < X4)               { src = x;  dh = xh;            off = id; }
    else if (id < X4 + W4)     { src = Wq; dh = wqkv;          off = id - X4; }
    else if (id < X4 + 2 * W4) { src = Wk; dh = wqkv + 4 * W4; off = id - X4 - W4; }
    else if (id < X4 + 3 * W4) { src = Wv; dh = wqkv + 8 * W4; off = id - X4 - 2 * W4; }
    else if (id < X4 + 4 * W4) { src = W1; dh = w1h;           off = id - X4 - 3 * W4; }
    else                       { src = W2; dh = w2h;           off = id - X4 - 4 * W4; }

    int i = off * 4;
    float4 v = *(const float4*)(src + i);
    *(__half2*)(dh + i)     = __halves2half2(__float2half(v.x), __float2half(v.y));
    *(__half2*)(dh + i + 2) = __halves2half2(__float2half(v.z), __float2half(v.w));
}

/* =========================================================================
 * Attention middle (exact fp32):  M_h = K_h^T V_h ;  OUT = Q_h @ M_h
 * ========================================================================= */
__global__ void __launch_bounds__(256)
kv_m_kernel(const float* __restrict__ K, const float* __restrict__ V,
            float* __restrict__ Mp)
{
    __shared__ float Ks[32][68];
    __shared__ float Vs[32][68];

    const int bh = blockIdx.x;               /* b*16 + h */
    const int b  = bh >> 4, h = bh & 15;
    const int s0 = blockIdx.y * 128;
    const int tid = threadIdx.x;
    const int e0 = (tid >> 4) * 4;
    const int d0 = (tid & 15) * 4;

    float acc[4][4] = {};

    for (int st = 0; st < 128; st += 32) {
#pragma unroll
        for (int p = 0; p < 2; p++) {
            int slot = tid + p * 256;            /* 0..511 */
            int lr = slot >> 4;                  /* 0..31  */
            int lc = (slot & 15) * 4;            /* 0..60  */
            size_t gi = ((size_t)(b * SEQ + s0 + st + lr)) * DIMC + h * HD + lc;
            *(float4*)&Ks[lr][lc] = *(const float4*)(K + gi);
            *(float4*)&Vs[lr][lc] = *(const float4*)(V + gi);
        }
        __syncthreads();
#pragma unroll
        for (int ss = 0; ss < 32; ss++) {
            float4 kv = *(const float4*)&Ks[ss][e0];
            float4 vv = *(const float4*)&Vs[ss][d0];
            float ka[4] = {kv.x, kv.y, kv.z, kv.w};
            float va[4] = {vv.x, vv.y, vv.z, vv.w};
#pragma unroll
            for (int i = 0; i < 4; i++)
#pragma unroll
                for (int jj = 0; jj < 4; jj++) acc[i][jj] += ka[i] * va[jj];
        }
        __syncthreads();
    }

    float* mo = Mp + ((size_t)blockIdx.y * 32 + bh) * (HD * HD);
#pragma unroll
    for (int i = 0; i < 4; i++)
#pragma unroll
        for (int jj = 0; jj < 4; jj++)
            mo[(e0 + i) * HD + d0 + jj] = acc[i][jj];
}

__global__ void reduce_m_kernel(const float* __restrict__ Mp, float* __restrict__ Mo)
{
    int i = blockIdx.x * 256 + threadIdx.x;
    float s = 0.0f;
#pragma unroll
    for (int p = 0; p < 16; p++) s += Mp[(size_t)p * 32 * HD * HD + i];
    Mo[i] = s;
}

/* OUT = Q @ M_h, fused fp16 output for the MLP GEMM */
__global__ void __launch_bounds__(256)
qm_kernel(const float* __restrict__ Q, const float* __restrict__ Mi,
          float* __restrict__ O, __half* __restrict__ Oh)
{
    __shared__ float Qs[64][68];
    __shared__ float Ms[64][68];

    const int bh = blockIdx.x;
    const int b  = bh >> 4, h = bh & 15;
    const int s0 = blockIdx.y * 64;
    const int tid = threadIdx.x;

#pragma unroll
    for (int p = 0; p < 4; p++) {
        int slot = tid + p * 256;
        int r = slot >> 4;
        int c = (slot & 15) * 4;
        *(float4*)&Qs[r][c] = *(const float4*)(Q + ((size_t)(b * SEQ + s0 + r)) * DIMC + h * HD + c);
        *(float4*)&Ms[r][c] = *(const float4*)(Mi + (size_t)bh * HD * HD + r * HD + c);
    }
    __syncthreads();

    const int r0 = (tid >> 4) * 4;
    const int c0 = (tid & 15) * 4;
    float acc[4][4] = {};
#pragma unroll
    for (int k = 0; k < 64; k++) {
        float qv[4], mv[4];
#pragma unroll
        for (int i = 0; i < 4; i++) qv[i] = Qs[r0 + i][k];
#pragma unroll
        for (int jj = 0; jj < 4; jj++) mv[jj] = Ms[k][c0 + jj];
#pragma unroll
        for (int i = 0; i < 4; i++)
#pragma unroll
            for (int jj = 0; jj < 4; jj++) acc[i][jj] += qv[i] * mv[jj];
    }
#pragma unroll
    for (int i = 0; i < 4; i++) {
        size_t base = ((size_t)(b * SEQ + s0 + r0 + i)) * DIMC + h * HD + c0;
#pragma unroll
        for (int jj = 0; jj < 4; jj++) O[base + jj] = acc[i][jj];
        *(__half2*)(Oh + base)     = __halves2half2(__float2half(acc[i][0]), __float2half(acc[i][1]));
        *(__half2*)(Oh + base + 2) = __halves2half2(__float2half(acc[i][2]), __float2half(acc[i][3]));
    }
}

/* ========================================================================= */
extern "C" void kernel_launch(void* const* d_in, const int* in_sizes, int n_in,
                              void* d_out, int out_size)
{
    const float* x  = (const float*)d_in[0];
    const float* Wq = (const float*)d_in[1];
    const float* bq = (const float*)d_in[2];
    const float* Wk = (const float*)d_in[3];
    const float* bk = (const float*)d_in[4];
    const float* Wv = (const float*)d_in[5];
    const float* bv = (const float*)d_in[6];
    const float* W1 = (const float*)d_in[7];
    const float* b1 = (const float*)d_in[8];
    const float* W2 = (const float*)d_in[9];
    const float* b2 = (const float*)d_in[10];
    float* Y = (float*)d_out;

    float *Q, *K, *V, *OUTP, *MP, *MM;
    cudaGetSymbolAddress((void**)&Q,    g_Q);
    cudaGetSymbolAddress((void**)&K,    g_K);
    cudaGetSymbolAddress((void**)&V,    g_V);
    cudaGetSymbolAddress((void**)&OUTP, g_OUT);
    cudaGetSymbolAddress((void**)&MP,   g_Mpart);
    cudaGetSymbolAddress((void**)&MM,   g_M);

    __half *xh, *oh, *hh, *wqkv, *w1h, *w2h;
    cudaGetSymbolAddress((void**)&xh,   g_xh);
    cudaGetSymbolAddress((void**)&oh,   g_oh);
    cudaGetSymbolAddress((void**)&hh,   g_hh);
    cudaGetSymbolAddress((void**)&wqkv, g_wqkv);
    cudaGetSymbolAddress((void**)&w1h,  g_w1h);
    cudaGetSymbolAddress((void**)&w2h,  g_w2h);

    cudaFuncSetAttribute(gemm_f16<3>, cudaFuncAttributeMaxDynamicSharedMemorySize, GSMEM);
    cudaFuncSetAttribute(gemm_f16<1>, cudaFuncAttributeMaxDynamicSharedMemorySize, GSMEM);
    cudaFuncSetAttribute(gemm_f16<2>, cudaFuncAttributeMaxDynamicSharedMemorySize, GSMEM);

    /* one conversion kernel: x + 5 weights -> fp16 */
    convert_all<<<CONV_BLOCKS, 256>>>(x, Wq, Wk, Wv, W1, W2,
                                      xh, wqkv, w1h, w2h);

    /* fused QKV projection: one GEMM over [4096 x 3072 x 1024], plain fp16 */
    dim3 qkvgrid(3 * DIMC / TN, MTOT / TM);   /* (24, 32) */
    gemm_f16<3><<<qkvgrid, NTHR, GSMEM>>>(xh, wqkv, bq, Q, nullptr,
                                          nullptr, nullptr, K, V, bk, bv);

    /* attention collapsed: out = Q @ (K^T V) per head, exact fp32 */
    kv_m_kernel<<<dim3(32, 16), 256>>>(K, V, MP);
    reduce_m_kernel<<<(32 * HD * HD) / 256, 256>>>(MP, MM);
    qm_kernel<<<dim3(32, SEQ / 64), 256>>>(Q, MM, OUTP, oh);

    /* MLP (plain fp16): h = gelu(OUT @ W1^T + b1); Y = x + OUT + h @ W2^T + b2 */
    dim3 ggrid(DIMC / TN, MTOT / TM);   /* (8, 32) */
    gemm_f16<1><<<ggrid, NTHR, GSMEM>>>(oh, w1h, b1, nullptr, hh,
                                        nullptr, nullptr, nullptr, nullptr, nullptr, nullptr);
    gemm_f16<2><<<ggrid, NTHR, GSMEM>>>(hh, w2h, b2, Y, nullptr,
                                        x, OUTP, nullptr, nullptr, nullptr, nullptr);
}